// round 1
// baseline (speedup 1.0000x reference)
#include <cuda_runtime.h>
#include <math.h>

#define NCOLS 3872
#define NROWS 32768
#define NGROUPS (NROWS / 4)

__device__ double g_sum[NCOLS];
__device__ double g_sumsq[NCOLS];
__device__ int g_selcol[512];

__device__ __forceinline__ void triu_pair(int p, int n, int &i, int &j) {
    int ii = 0, rem = p, cnt = n - 1;
    while (rem >= cnt) { rem -= cnt; cnt--; ii++; }
    i = ii; j = ii + 1 + rem;
}

// Column descriptor: kind<<24 | a<<12 | b
// kinds: 0 zn(clipped), 1 zn^2, 2 sin, 3 cos, 4 log|zn|+1e-3, 5 exp(clip),
//        6 p_sq (a = node*8), 7 product zn[a]*zn[b], 16+chunk = dist chunk
__device__ __forceinline__ int decode(int c) {
    int kind, a, b = 0;
    if (c < 128)       { kind = 0; a = c; }
    else if (c < 1808) { int q = c - 128; kind = 16 + q / 120; a = q % 120; }
    else if (c < 1936) { kind = 1; a = c - 1808; }
    else if (c < 2064) { kind = 2; a = c - 1936; }
    else if (c < 2192) { kind = 3; a = c - 2064; }
    else if (c < 2320) { kind = 4; a = c - 2192; }
    else if (c < 2448) { kind = 5; a = c - 2320; }
    else if (c < 2464) { kind = 6; a = (c - 2448) * 8; }
    else if (c < 2912) {
        int idx = c - 2464; int n = idx / 28, pr = idx % 28;
        int i, j; triu_pair(pr, 8, i, j);
        kind = 7; a = n * 8 + i; b = n * 8 + j;
    } else {
        int idx = c - 2912; int pr = idx / 8, k = idx % 8;
        int i, j; triu_pair(pr, 16, i, j);
        kind = 7; a = i * 8 + k; b = j * 8 + k;
    }
    return (kind << 24) | (a << 12) | b;
}

__device__ __forceinline__ float evalcol(int desc, const float* __restrict__ zn,
                                         const float* __restrict__ dv) {
    int kind = desc >> 24;
    int a = (desc >> 12) & 0xFFF;
    int b = desc & 0xFFF;
    float v;
    if (kind >= 16) {
        float dd = dv[a];
        int ch = kind - 16;
        switch (ch) {
            case 0: v = dd; break;
            case 1: v = 1.0f / (dd + 1e-3f); break;
            case 2: v = 1.0f / (dd * dd + 1e-3f); break;
            case 3: { float d2 = dd * dd; v = 1.0f / (d2 * dd + 1e-3f); } break;
            case 4: { float d2 = dd * dd; v = 1.0f / (d2 * d2 + 1e-3f); } break;
            case 5: { float d2 = dd * dd; v = 1.0f / (d2 * d2 * dd + 1e-3f); } break;
            case 6: { float d2 = dd * dd; float d4 = d2 * d2; v = 1.0f / (d4 * d2 + 1e-3f); } break;
            case 7: { float d2 = dd * dd; float d4 = d2 * d2; v = 1.0f / (d4 * d4 + 1e-3f); } break;
            case 8: { float d2 = dd * dd; float d4 = d2 * d2; v = 1.0f / (d4 * d4 * d2 + 1e-3f); } break;
            case 9: { float d2 = dd * dd; float d4 = d2 * d2; v = 1.0f / (d4 * d4 * d4 + 1e-3f); } break;
            case 10:{ float d2 = dd * dd; float d4 = d2 * d2; float d8 = d4 * d4;
                      v = 1.0f / (d8 * d4 * d2 + 1e-3f); } break;
            case 11: v = expf(-dd); break;
            case 12: v = expf(-dd) / (dd + 1e-3f); break;
            default: v = logf(dd + 1e-3f); break;
        }
        return fminf(fmaxf(v, -1e6f), 1e6f);  // X is clipped at +-1e6
    }
    switch (kind) {
        case 0: v = fminf(fmaxf(zn[a], -1e6f), 1e6f); break;
        case 1: { float t = zn[a]; v = t * t; } break;
        case 2: v = sinf(zn[a]); break;
        case 3: v = cosf(zn[a]); break;
        case 4: v = logf(fabsf(zn[a]) + 1e-3f); break;
        case 5: v = expf(fminf(fmaxf(zn[a], -10.0f), 2.0f)); break;
        case 6: { float s = 0.0f;
                  #pragma unroll
                  for (int k = 4; k < 8; k++) { float t = zn[a + k]; s += t * t; }
                  v = s; } break;
        default: v = zn[a] * zn[b]; break;
    }
    return v;
}

__global__ void zero_kernel() {
    int i = blockIdx.x * blockDim.x + threadIdx.x;
    if (i < NCOLS) { g_sum[i] = 0.0; g_sumsq[i] = 0.0; }
}

__global__ void __launch_bounds__(512, 1)
pass1_kernel(const float* __restrict__ z_flat,
             const float* __restrict__ z_mean,
             const float* __restrict__ z_std) {
    __shared__ float s_zn[4][128];
    __shared__ float s_zp[4][32];
    __shared__ float s_d[4][120];
    const int tid = threadIdx.x;

    int desc[8];
    #pragma unroll
    for (int k = 0; k < 8; k++) {
        int c = tid + k * 512;
        desc[k] = (c < NCOLS) ? decode(c) : 0;
    }
    float fs[8], fq[8];
    double dsm[8], dsq[8];
    #pragma unroll
    for (int k = 0; k < 8; k++) { fs[k] = 0.f; fq[k] = 0.f; dsm[k] = 0.0; dsq[k] = 0.0; }

    const int r_a = tid >> 7, c_a = tid & 127;
    const float zm = z_mean[c_a];
    const float zs = z_std[c_a];
    const int br = tid / 120, bp = tid - br * 120;
    int bi = 0, bj = 0;
    if (tid < 480) triu_pair(bp, 16, bi, bj);

    int iter = 0;
    for (int g = blockIdx.x; g < NGROUPS; g += gridDim.x) {
        {
            float z = z_flat[(g * 4 + r_a) * 128 + c_a];
            z = fminf(fmaxf(z, -1e6f), 1e6f);
            s_zn[r_a][c_a] = (z - zm) / zs;
            if ((c_a & 7) < 2) s_zp[r_a][((c_a >> 3) << 1) | (c_a & 7)] = z;
        }
        __syncthreads();
        if (tid < 480) {
            float dx = s_zp[br][2 * bi]     - s_zp[br][2 * bj];
            float dy = s_zp[br][2 * bi + 1] - s_zp[br][2 * bj + 1];
            dx -= 10.0f * rintf(dx * 0.1f);
            dy -= 10.0f * rintf(dy * 0.1f);
            s_d[br][bp] = sqrtf(dx * dx + dy * dy) + 1e-6f;
        }
        __syncthreads();
        #pragma unroll
        for (int r = 0; r < 4; r++) {
            const float* zn = s_zn[r];
            const float* dv = s_d[r];
            #pragma unroll
            for (int k = 0; k < 8; k++) {
                if (tid + k * 512 < NCOLS) {
                    float v = evalcol(desc[k], zn, dv);
                    fs[k] += v;
                    fq[k] = fmaf(v, v, fq[k]);
                }
            }
        }
        __syncthreads();
        if ((++iter & 1) == 0) {
            #pragma unroll
            for (int k = 0; k < 8; k++) {
                dsm[k] += (double)fs[k]; fs[k] = 0.f;
                dsq[k] += (double)fq[k]; fq[k] = 0.f;
            }
        }
    }
    #pragma unroll
    for (int k = 0; k < 8; k++) {
        int c = tid + k * 512;
        if (c < NCOLS) {
            dsm[k] += (double)fs[k];
            dsq[k] += (double)fq[k];
            atomicAdd(&g_sum[c], dsm[k]);
            atomicAdd(&g_sumsq[c], dsq[k]);
        }
    }
}

__global__ void __launch_bounds__(1024, 1)
topk_kernel(const int* __restrict__ feature_mask) {
    __shared__ unsigned long long keys[4096];
    __shared__ int s_top[1000];
    const int tid = threadIdx.x;
    for (int c = tid; c < 4096; c += 1024) {
        unsigned long long key = 0ull;
        if (c < NCOLS) {
            double s = g_sum[c], q = g_sumsq[c];
            double var = (q - s * (s * (1.0 / 32768.0))) * (1.0 / 32767.0);
            float fv = (float)var;
            unsigned u = __float_as_uint(fv);
            u = (u & 0x80000000u) ? ~u : (u | 0x80000000u);
            key = ((unsigned long long)u << 32) |
                  (unsigned long long)(0xFFFFFFFFu - (unsigned)c);
        }
        keys[c] = key;
    }
    __syncthreads();
    // bitonic sort, descending; ties -> lower index first (via ~idx low bits)
    for (int k = 2; k <= 4096; k <<= 1) {
        for (int j = k >> 1; j > 0; j >>= 1) {
            for (int i = tid; i < 4096; i += 1024) {
                int ixj = i ^ j;
                if (ixj > i) {
                    unsigned long long a = keys[i], bb = keys[ixj];
                    bool up = ((i & k) == 0);
                    bool sw = up ? (a < bb) : (a > bb);
                    if (sw) { keys[i] = bb; keys[ixj] = a; }
                }
            }
            __syncthreads();
        }
    }
    for (int r = tid; r < 1000; r += 1024)
        s_top[r] = (int)(0xFFFFFFFFu - (unsigned)(keys[r] & 0xFFFFFFFFull));
    __syncthreads();
    if (tid < 512) g_selcol[tid] = s_top[feature_mask[tid]];
}

__global__ void __launch_bounds__(512, 2)
gather_kernel(const float* __restrict__ z_flat,
              const float* __restrict__ z_mean,
              const float* __restrict__ z_std,
              const float* __restrict__ x_poly_mean,
              const float* __restrict__ x_poly_std,
              const int* __restrict__ feature_mask,
              float* __restrict__ out) {
    __shared__ float s_zn[4][128];
    __shared__ float s_zp[4][32];
    __shared__ float s_d[4][120];
    const int tid = threadIdx.x;
    const int desc = decode(g_selcol[tid]);
    const int m = feature_mask[tid];
    const float mj = x_poly_mean[m];
    const float sj = x_poly_std[m];

    const int r_a = tid >> 7, c_a = tid & 127;
    const float zm = z_mean[c_a];
    const float zs = z_std[c_a];
    const int br = tid / 120, bp = tid - br * 120;
    int bi = 0, bj = 0;
    if (tid < 480) triu_pair(bp, 16, bi, bj);

    for (int g = blockIdx.x; g < NGROUPS; g += gridDim.x) {
        {
            float z = z_flat[(g * 4 + r_a) * 128 + c_a];
            z = fminf(fmaxf(z, -1e6f), 1e6f);
            s_zn[r_a][c_a] = (z - zm) / zs;
            if ((c_a & 7) < 2) s_zp[r_a][((c_a >> 3) << 1) | (c_a & 7)] = z;
        }
        __syncthreads();
        if (tid < 480) {
            float dx = s_zp[br][2 * bi]     - s_zp[br][2 * bj];
            float dy = s_zp[br][2 * bi + 1] - s_zp[br][2 * bj + 1];
            dx -= 10.0f * rintf(dx * 0.1f);
            dy -= 10.0f * rintf(dy * 0.1f);
            s_d[br][bp] = sqrtf(dx * dx + dy * dy) + 1e-6f;
        }
        __syncthreads();
        #pragma unroll
        for (int r = 0; r < 4; r++) {
            float v = evalcol(desc, s_zn[r], s_d[r]);
            if (isnan(v)) v = 0.0f;
            else if (isinf(v)) v = (v > 0.0f) ? 1e9f : -1e9f;
            v = fminf(fmaxf(v, -1e12f), 1e12f);
            out[(g * 4 + r) * 512 + tid] = (v - mj) / sj;
        }
        __syncthreads();
    }
}

extern "C" void kernel_launch(void* const* d_in, const int* in_sizes, int n_in,
                              void* d_out, int out_size) {
    const float* z_flat      = (const float*)d_in[0];
    const float* z_mean      = (const float*)d_in[1];
    const float* z_std       = (const float*)d_in[2];
    const float* x_poly_mean = (const float*)d_in[3];
    const float* x_poly_std  = (const float*)d_in[4];
    const int*   feature_mask = (const int*)d_in[5];
    float* out = (float*)d_out;

    zero_kernel<<<16, 256>>>();
    pass1_kernel<<<148, 512>>>(z_flat, z_mean, z_std);
    topk_kernel<<<1, 1024>>>(feature_mask);
    gather_kernel<<<296, 512>>>(z_flat, z_mean, z_std,
                                x_poly_mean, x_poly_std, feature_mask, out);
}

// round 2
// speedup vs baseline: 1.4865x; 1.4865x over previous
#include <cuda_runtime.h>
#include <math.h>

#define NCOLS 3872
#define NROWS 32768
#define NG8 (NROWS / 8)

__device__ double g_sum[NCOLS];
__device__ double g_sumsq[NCOLS];
__device__ int g_selcol[512];

__device__ __forceinline__ float frcp(float x) {
    float r; asm("rcp.approx.f32 %0, %1;" : "=f"(r) : "f"(x)); return r;
}
__device__ __forceinline__ float fsqrt_a(float x) {
    float r; asm("sqrt.approx.f32 %0, %1;" : "=f"(r) : "f"(x)); return r;
}

__device__ __forceinline__ void triu_pair(int p, int n, int &i, int &j) {
    int ii = 0, rem = p, cnt = n - 1;
    while (rem >= cnt) { rem -= cnt; cnt--; ii++; }
    i = ii; j = ii + 1 + rem;
}

// Column descriptor: kind<<24 | a<<12 | b
// kinds: 0 zn(clipped), 1 zn^2, 2 sin, 3 cos, 4 log|zn|+1e-3, 5 exp(clip),
//        6 p_sq (a = node*8), 7 product zn[a]*zn[b], 16+chunk = dist chunk
__device__ __forceinline__ int decode(int c) {
    int kind, a, b = 0;
    if (c < 128)       { kind = 0; a = c; }
    else if (c < 1808) { int q = c - 128; kind = 16 + q / 120; a = q % 120; }
    else if (c < 1936) { kind = 1; a = c - 1808; }
    else if (c < 2064) { kind = 2; a = c - 1936; }
    else if (c < 2192) { kind = 3; a = c - 2064; }
    else if (c < 2320) { kind = 4; a = c - 2192; }
    else if (c < 2448) { kind = 5; a = c - 2320; }
    else if (c < 2464) { kind = 6; a = (c - 2448) * 8; }
    else if (c < 2912) {
        int idx = c - 2464; int n = idx / 28, pr = idx % 28;
        int i, j; triu_pair(pr, 8, i, j);
        kind = 7; a = n * 8 + i; b = n * 8 + j;
    } else {
        int idx = c - 2912; int pr = idx / 8, k = idx % 8;
        int i, j; triu_pair(pr, 16, i, j);
        kind = 7; a = i * 8 + k; b = j * 8 + k;
    }
    return (kind << 24) | (a << 12) | b;
}

__device__ __forceinline__ float evalcol(int desc, const float* __restrict__ zn,
                                         const float* __restrict__ dv) {
    int kind = desc >> 24;
    int a = (desc >> 12) & 0xFFF;
    int b = desc & 0xFFF;
    float v;
    if (kind >= 16) {
        float dd = dv[a];
        int ch = kind - 16;
        switch (ch) {
            case 0: v = dd; break;
            case 1: v = frcp(dd + 1e-3f); break;
            case 2: v = frcp(dd * dd + 1e-3f); break;
            case 3: { float d2 = dd * dd; v = frcp(d2 * dd + 1e-3f); } break;
            case 4: { float d2 = dd * dd; v = frcp(d2 * d2 + 1e-3f); } break;
            case 5: { float d2 = dd * dd; v = frcp(d2 * d2 * dd + 1e-3f); } break;
            case 6: { float d2 = dd * dd; float d4 = d2 * d2; v = frcp(d4 * d2 + 1e-3f); } break;
            case 7: { float d2 = dd * dd; float d4 = d2 * d2; v = frcp(d4 * d4 + 1e-3f); } break;
            case 8: { float d2 = dd * dd; float d4 = d2 * d2; v = frcp(d4 * d4 * d2 + 1e-3f); } break;
            case 9: { float d2 = dd * dd; float d4 = d2 * d2; v = frcp(d4 * d4 * d4 + 1e-3f); } break;
            case 10:{ float d2 = dd * dd; float d4 = d2 * d2; float d8 = d4 * d4;
                      v = frcp(d8 * d4 * d2 + 1e-3f); } break;
            case 11: v = __expf(-dd); break;
            case 12: v = __expf(-dd) * frcp(dd + 1e-3f); break;
            default: v = __logf(dd + 1e-3f); break;
        }
        return fminf(fmaxf(v, -1e6f), 1e6f);  // X is clipped at +-1e6
    }
    switch (kind) {
        case 0: v = fminf(fmaxf(zn[a], -1e6f), 1e6f); break;
        case 1: { float t = zn[a]; v = t * t; } break;
        case 2: v = __sinf(zn[a]); break;
        case 3: v = __cosf(zn[a]); break;
        case 4: v = __logf(fabsf(zn[a]) + 1e-3f); break;
        case 5: v = __expf(fminf(fmaxf(zn[a], -10.0f), 2.0f)); break;
        case 6: { float s = 0.0f;
                  #pragma unroll
                  for (int k = 4; k < 8; k++) { float t = zn[a + k]; s += t * t; }
                  v = s; } break;
        default: v = zn[a] * zn[b]; break;
    }
    return v;
}

__global__ void zero_kernel() {
    int i = blockIdx.x * blockDim.x + threadIdx.x;
    if (i < NCOLS) { g_sum[i] = 0.0; g_sumsq[i] = 0.0; }
}

__global__ void __launch_bounds__(1024, 1)
pass1_kernel(const float* __restrict__ z_flat,
             const float* __restrict__ z_mean,
             const float* __restrict__ z_std) {
    __shared__ float s_zn[8][128];
    __shared__ float s_zp[8][32];
    __shared__ float s_d[8][120];
    const int tid = threadIdx.x;

    int desc[4];
    #pragma unroll
    for (int k = 0; k < 4; k++) {
        int c = tid + k * 1024;
        desc[k] = (c < NCOLS) ? decode(c) : decode(0);
    }
    const bool valid3 = (tid < NCOLS - 3072);

    float fs[4], fq[4];
    double dsm[4], dsq[4];
    #pragma unroll
    for (int k = 0; k < 4; k++) { fs[k] = 0.f; fq[k] = 0.f; dsm[k] = 0.0; dsq[k] = 0.0; }

    const int r_a = tid >> 7, c_a = tid & 127;
    const float zm = z_mean[c_a];
    const float zs_inv = frcp(z_std[c_a]);
    const int br = tid / 120, bp = tid - br * 120;
    int bi = 0, bj = 0;
    if (tid < 960) triu_pair(bp, 16, bi, bj);

    for (int g = blockIdx.x; g < NG8; g += gridDim.x) {
        {
            float z = z_flat[(g * 8 + r_a) * 128 + c_a];
            z = fminf(fmaxf(z, -1e6f), 1e6f);
            s_zn[r_a][c_a] = (z - zm) * zs_inv;
            if ((c_a & 7) < 2) s_zp[r_a][((c_a >> 3) << 1) | (c_a & 7)] = z;
        }
        __syncthreads();
        if (tid < 960) {
            float dx = s_zp[br][2 * bi]     - s_zp[br][2 * bj];
            float dy = s_zp[br][2 * bi + 1] - s_zp[br][2 * bj + 1];
            dx -= 10.0f * rintf(dx * 0.1f);
            dy -= 10.0f * rintf(dy * 0.1f);
            s_d[br][bp] = fsqrt_a(dx * dx + dy * dy) + 1e-6f;
        }
        __syncthreads();
        #pragma unroll
        for (int r = 0; r < 8; r++) {
            const float* zn = s_zn[r];
            const float* dv = s_d[r];
            #pragma unroll
            for (int k = 0; k < 3; k++) {
                float v = evalcol(desc[k], zn, dv);
                fs[k] += v;
                fq[k] = fmaf(v, v, fq[k]);
            }
            if (valid3) {
                float v = evalcol(desc[3], zn, dv);
                fs[3] += v;
                fq[3] = fmaf(v, v, fq[3]);
            }
        }
        __syncthreads();
        #pragma unroll
        for (int k = 0; k < 4; k++) {
            dsm[k] += (double)fs[k]; fs[k] = 0.f;
            dsq[k] += (double)fq[k]; fq[k] = 0.f;
        }
    }
    #pragma unroll
    for (int k = 0; k < 4; k++) {
        int c = tid + k * 1024;
        if (c < NCOLS) {
            atomicAdd(&g_sum[c], dsm[k]);
            atomicAdd(&g_sumsq[c], dsq[k]);
        }
    }
}

__global__ void __launch_bounds__(1024, 1)
topk_kernel(const int* __restrict__ feature_mask) {
    __shared__ unsigned long long keys[4096];
    __shared__ int s_top[1000];
    const int tid = threadIdx.x;
    for (int c = tid; c < 4096; c += 1024) {
        unsigned long long key = 0ull;
        if (c < NCOLS) {
            double s = g_sum[c], q = g_sumsq[c];
            double var = (q - s * (s * (1.0 / 32768.0))) * (1.0 / 32767.0);
            float fv = (float)var;
            unsigned u = __float_as_uint(fv);
            u = (u & 0x80000000u) ? ~u : (u | 0x80000000u);
            key = ((unsigned long long)u << 32) |
                  (unsigned long long)(0xFFFFFFFFu - (unsigned)c);
        }
        keys[c] = key;
    }
    __syncthreads();
    // bitonic sort, descending; ties -> lower index first (via ~idx low bits)
    for (int k = 2; k <= 4096; k <<= 1) {
        for (int j = k >> 1; j > 0; j >>= 1) {
            for (int i = tid; i < 4096; i += 1024) {
                int ixj = i ^ j;
                if (ixj > i) {
                    unsigned long long a = keys[i], bb = keys[ixj];
                    bool up = ((i & k) == 0);
                    bool sw = up ? (a < bb) : (a > bb);
                    if (sw) { keys[i] = bb; keys[ixj] = a; }
                }
            }
            __syncthreads();
        }
    }
    for (int r = tid; r < 1000; r += 1024)
        s_top[r] = (int)(0xFFFFFFFFu - (unsigned)(keys[r] & 0xFFFFFFFFull));
    __syncthreads();
    if (tid < 512) g_selcol[tid] = s_top[feature_mask[tid]];
}

__global__ void __launch_bounds__(1024, 1)
gather_kernel(const float* __restrict__ z_flat,
              const float* __restrict__ z_mean,
              const float* __restrict__ z_std,
              const float* __restrict__ x_poly_mean,
              const float* __restrict__ x_poly_std,
              const int* __restrict__ feature_mask,
              float* __restrict__ out) {
    __shared__ float s_zn[8][128];
    __shared__ float s_zp[8][32];
    __shared__ float s_d[8][120];
    const int tid = threadIdx.x;
    const int col = tid & 511;
    const int rp = tid >> 9;   // 0 or 1
    const int desc = decode(g_selcol[col]);
    const int m = feature_mask[col];
    const float mj = x_poly_mean[m];
    const float sj_inv = frcp(x_poly_std[m]);

    const int r_a = tid >> 7, c_a = tid & 127;
    const float zm = z_mean[c_a];
    const float zs_inv = frcp(z_std[c_a]);
    const int br = tid / 120, bp = tid - br * 120;
    int bi = 0, bj = 0;
    if (tid < 960) triu_pair(bp, 16, bi, bj);

    for (int g = blockIdx.x; g < NG8; g += gridDim.x) {
        {
            float z = z_flat[(g * 8 + r_a) * 128 + c_a];
            z = fminf(fmaxf(z, -1e6f), 1e6f);
            s_zn[r_a][c_a] = (z - zm) * zs_inv;
            if ((c_a & 7) < 2) s_zp[r_a][((c_a >> 3) << 1) | (c_a & 7)] = z;
        }
        __syncthreads();
        if (tid < 960) {
            float dx = s_zp[br][2 * bi]     - s_zp[br][2 * bj];
            float dy = s_zp[br][2 * bi + 1] - s_zp[br][2 * bj + 1];
            dx -= 10.0f * rintf(dx * 0.1f);
            dy -= 10.0f * rintf(dy * 0.1f);
            s_d[br][bp] = fsqrt_a(dx * dx + dy * dy) + 1e-6f;
        }
        __syncthreads();
        #pragma unroll
        for (int rr = 0; rr < 4; rr++) {
            int row = rr * 2 + rp;
            float v = evalcol(desc, s_zn[row], s_d[row]);
            if (isnan(v)) v = 0.0f;
            else if (isinf(v)) v = (v > 0.0f) ? 1e9f : -1e9f;
            v = fminf(fmaxf(v, -1e12f), 1e12f);
            out[(g * 8 + row) * 512 + col] = (v - mj) * sj_inv;
        }
        __syncthreads();
    }
}

extern "C" void kernel_launch(void* const* d_in, const int* in_sizes, int n_in,
                              void* d_out, int out_size) {
    const float* z_flat      = (const float*)d_in[0];
    const float* z_mean      = (const float*)d_in[1];
    const float* z_std       = (const float*)d_in[2];
    const float* x_poly_mean = (const float*)d_in[3];
    const float* x_poly_std  = (const float*)d_in[4];
    const int*   feature_mask = (const int*)d_in[5];
    float* out = (float*)d_out;

    zero_kernel<<<16, 256>>>();
    pass1_kernel<<<148, 1024>>>(z_flat, z_mean, z_std);
    topk_kernel<<<1, 1024>>>(feature_mask);
    gather_kernel<<<148, 1024>>>(z_flat, z_mean, z_std,
                                 x_poly_mean, x_poly_std, feature_mask, out);
}

// round 3
// speedup vs baseline: 1.8675x; 1.2563x over previous
#include <cuda_runtime.h>
#include <math.h>

#define NCOLS 3872
#define NROWS 32768
#define NG4   (NROWS / 4)
#define GRID_P 444
#define NDV 3360            // 120 pairs * 28 (14 sum + 14 sumsq)
#define NRV 2192            // non-dist columns

__device__ float  g_scr_d[GRID_P * NDV];
__device__ float  g_scr_r[GRID_P * NRV * 2];
__device__ double g_sum[NCOLS];
__device__ double g_sumsq[NCOLS];
__device__ int    g_sel_desc[512];
__device__ int    g_sel_j[512];

__device__ __forceinline__ float frcp(float x) {
    float r; asm("rcp.approx.f32 %0, %1;" : "=f"(r) : "f"(x)); return r;
}
__device__ __forceinline__ float fsqrt_a(float x) {
    float r; asm("sqrt.approx.f32 %0, %1;" : "=f"(r) : "f"(x)); return r;
}

__device__ __forceinline__ void triu_pair(int p, int n, int &i, int &j) {
    int ii = 0, rem = p, cnt = n - 1;
    while (rem >= cnt) { rem -= cnt; cnt--; ii++; }
    i = ii; j = ii + 1 + rem;
}

// Column descriptor: kind<<24 | a<<12 | b
// kinds: 0 zn, 1 zn^2, 2 sin, 3 cos, 4 log|zn|+1e-3, 5 exp(clip),
//        6 p_sq (a = node*8), 7 product zn[a]*zn[b], 16+chunk = dist chunk
__device__ __forceinline__ int decode(int c) {
    int kind, a, b = 0;
    if (c < 128)       { kind = 0; a = c; }
    else if (c < 1808) { int q = c - 128; kind = 16 + q / 120; a = q % 120; }
    else if (c < 1936) { kind = 1; a = c - 1808; }
    else if (c < 2064) { kind = 2; a = c - 1936; }
    else if (c < 2192) { kind = 3; a = c - 2064; }
    else if (c < 2320) { kind = 4; a = c - 2192; }
    else if (c < 2448) { kind = 5; a = c - 2320; }
    else if (c < 2464) { kind = 6; a = (c - 2448) * 8; }
    else if (c < 2912) {
        int idx = c - 2464; int n = idx / 28, pr = idx % 28;
        int i, j; triu_pair(pr, 8, i, j);
        kind = 7; a = n * 8 + i; b = n * 8 + j;
    } else {
        int idx = c - 2912; int pr = idx / 8, k = idx % 8;
        int i, j; triu_pair(pr, 16, i, j);
        kind = 7; a = i * 8 + k; b = j * 8 + k;
    }
    return (kind << 24) | (a << 12) | b;
}

// non-dist column evaluation (kind < 16)
__device__ __forceinline__ float evalrest(int desc, const float* __restrict__ zn) {
    int kind = desc >> 24;
    int a = (desc >> 12) & 0xFFF;
    int b = desc & 0xFFF;
    float v;
    switch (kind) {
        case 0: v = zn[a]; break;
        case 1: { float t = zn[a]; v = t * t; } break;
        case 2: v = __sinf(zn[a]); break;
        case 3: v = __cosf(zn[a]); break;
        case 4: v = __logf(fabsf(zn[a]) + 1e-3f); break;
        case 5: v = __expf(fminf(fmaxf(zn[a], -10.0f), 2.0f)); break;
        case 6: { float s = 0.0f;
                  #pragma unroll
                  for (int k = 4; k < 8; k++) { float t = zn[a + k]; s += t * t; }
                  v = s; } break;
        default: v = zn[a] * zn[b]; break;
    }
    return v;
}

// full evaluation (gather): dist kinds read dv
__device__ __forceinline__ float evalcol(int desc, const float* __restrict__ zn,
                                         const float* __restrict__ dv) {
    int kind = desc >> 24;
    if (kind >= 16) {
        int a = (desc >> 12) & 0xFFF;
        float dd = dv[a];
        float v;
        switch (kind - 16) {
            case 0: v = dd; break;
            case 1: v = frcp(dd + 1e-3f); break;
            case 2: v = frcp(dd * dd + 1e-3f); break;
            case 3: { float d2 = dd * dd; v = frcp(d2 * dd + 1e-3f); } break;
            case 4: { float d2 = dd * dd; v = frcp(d2 * d2 + 1e-3f); } break;
            case 5: { float d2 = dd * dd; v = frcp(d2 * d2 * dd + 1e-3f); } break;
            case 6: { float d2 = dd * dd; float d4 = d2 * d2; v = frcp(d4 * d2 + 1e-3f); } break;
            case 7: { float d2 = dd * dd; float d4 = d2 * d2; v = frcp(d4 * d4 + 1e-3f); } break;
            case 8: { float d2 = dd * dd; float d4 = d2 * d2; v = frcp(d4 * d4 * d2 + 1e-3f); } break;
            case 9: { float d2 = dd * dd; float d4 = d2 * d2; v = frcp(d4 * d4 * d4 + 1e-3f); } break;
            case 10:{ float d2 = dd * dd; float d4 = d2 * d2; float d8 = d4 * d4;
                      v = frcp(d8 * d4 * d2 + 1e-3f); } break;
            case 11: v = __expf(-dd); break;
            case 12: v = __expf(-dd) * frcp(dd + 1e-3f); break;
            default: v = __logf(dd + 1e-3f); break;
        }
        return fminf(fmaxf(v, -1e6f), 1e6f);
    }
    return evalrest(desc, zn);
}

// ---------------- pass 1a: distance-derived columns (shared power chain) ----
__global__ void __launch_bounds__(512, 2)
p1dist_kernel(const float* __restrict__ z_flat) {
    __shared__ float s_zp[4][32];
    __shared__ float s_red[NDV];
    const int tid = threadIdx.x;
    const int r_a = tid >> 7, c_a = tid & 127;
    const int bp = tid % 120, br = tid / 120;
    int bi = 0, bj = 0;
    if (tid < 480) triu_pair(bp, 16, bi, bj);

    float acc[28];
    #pragma unroll
    for (int k = 0; k < 28; k++) acc[k] = 0.f;

    for (int g = blockIdx.x; g < NG4; g += GRID_P) {
        float z = z_flat[(g * 4 + r_a) * 128 + c_a];
        z = fminf(fmaxf(z, -1e6f), 1e6f);
        if ((c_a & 7) < 2) s_zp[r_a][((c_a >> 3) << 1) | (c_a & 7)] = z;
        __syncthreads();
        if (tid < 480) {
            float dx = s_zp[br][2 * bi]     - s_zp[br][2 * bj];
            float dy = s_zp[br][2 * bi + 1] - s_zp[br][2 * bj + 1];
            dx -= 10.0f * rintf(dx * 0.1f);
            dy -= 10.0f * rintf(dy * 0.1f);
            float d = fsqrt_a(dx * dx + dy * dy) + 1e-6f;
            float dpe = d + 1e-3f;
            float r1 = frcp(dpe);
            float d2 = d * d, d3 = d2 * d, d4 = d2 * d2, d6 = d3 * d3, d8 = d4 * d4;
            float v[14];
            v[0] = d;
            v[1] = r1;
            v[2] = frcp(d2 + 1e-3f);
            v[3] = frcp(d3 + 1e-3f);
            v[4] = frcp(d4 + 1e-3f);
            v[5] = frcp(d4 * d + 1e-3f);
            v[6] = frcp(d6 + 1e-3f);
            v[7] = frcp(d8 + 1e-3f);
            v[8] = frcp(d8 * d2 + 1e-3f);
            v[9] = frcp(d6 * d6 + 1e-3f);
            v[10] = frcp(d8 * d6 + 1e-3f);
            float e = __expf(-d);
            v[11] = e;
            v[12] = e * r1;
            v[13] = __logf(dpe);
            #pragma unroll
            for (int k = 0; k < 14; k++) {
                acc[k] += v[k];
                acc[14 + k] = fmaf(v[k], v[k], acc[14 + k]);
            }
        }
        __syncthreads();
    }
    // reduce the 4 row-slots per pair
    if (tid < 480 && br == 0) {
        #pragma unroll
        for (int k = 0; k < 28; k++) s_red[bp * 28 + k] = acc[k];
    }
    __syncthreads();
    for (int s = 1; s < 4; s++) {
        if (tid < 480 && br == s) {
            #pragma unroll
            for (int k = 0; k < 28; k++) s_red[bp * 28 + k] += acc[k];
        }
        __syncthreads();
    }
    for (int v = tid; v < NDV; v += 512)
        g_scr_d[blockIdx.x * NDV + v] = s_red[v];
}

// ---------------- pass 1b: all non-distance columns ------------------------
__global__ void __launch_bounds__(512, 2)
p1rest_kernel(const float* __restrict__ z_flat,
              const float* __restrict__ z_mean,
              const float* __restrict__ z_std) {
    __shared__ float s_zn[4][128];
    const int tid = threadIdx.x;
    const int r_a = tid >> 7, c_a = tid & 127;
    const float zm = z_mean[c_a];
    const float zsi = frcp(z_std[c_a]);

    int desc[5]; bool val[5];
    #pragma unroll
    for (int k = 0; k < 5; k++) {
        int i = tid + k * 512;
        val[k] = (i < NRV);
        int col = (i < 128) ? i : i + 1680;
        desc[k] = val[k] ? decode(col) : 0;
    }
    float fs[5], fq[5];
    #pragma unroll
    for (int k = 0; k < 5; k++) { fs[k] = 0.f; fq[k] = 0.f; }

    for (int g = blockIdx.x; g < NG4; g += GRID_P) {
        float z = z_flat[(g * 4 + r_a) * 128 + c_a];
        z = fminf(fmaxf(z, -1e6f), 1e6f);
        s_zn[r_a][c_a] = (z - zm) * zsi;
        __syncthreads();
        #pragma unroll
        for (int r = 0; r < 4; r++) {
            const float* zn = s_zn[r];
            #pragma unroll
            for (int k = 0; k < 5; k++) {
                if (val[k]) {
                    float v = evalrest(desc[k], zn);
                    fs[k] += v;
                    fq[k] = fmaf(v, v, fq[k]);
                }
            }
        }
        __syncthreads();
    }
    #pragma unroll
    for (int k = 0; k < 5; k++) {
        int i = tid + k * 512;
        if (val[k]) {
            g_scr_r[blockIdx.x * (2 * NRV) + i] = fs[k];
            g_scr_r[blockIdx.x * (2 * NRV) + NRV + i] = fq[k];
        }
    }
}

// ---------------- reduce partials into f64 sums -----------------------------
__global__ void reduce_kernel() {
    int v = blockIdx.x * blockDim.x + threadIdx.x;
    if (v < NDV) {
        double s = 0.0;
        for (int b = 0; b < GRID_P; b++) s += (double)g_scr_d[b * NDV + v];
        int pair = v / 28, k = v % 28;
        int col = 128 + (k % 14) * 120 + pair;
        if (k < 14) g_sum[col] = s; else g_sumsq[col] = s;
    } else if (v < NDV + 2 * NRV) {
        int i = v - NDV;
        double s = 0.0;
        for (int b = 0; b < GRID_P; b++) s += (double)g_scr_r[b * 2 * NRV + i];
        int ii = (i < NRV) ? i : i - NRV;
        int col = (ii < 128) ? ii : ii + 1680;
        if (i < NRV) g_sum[col] = s; else g_sumsq[col] = s;
    }
}

// ---------------- top-k + selection + class-sorted permutation -------------
__global__ void __launch_bounds__(1024, 1)
topk_kernel(const int* __restrict__ feature_mask) {
    __shared__ unsigned long long keys[4096];
    __shared__ int s_top[1000];
    __shared__ int s_selcol[512];
    __shared__ unsigned s_key[512];
    const int tid = threadIdx.x;
    for (int c = tid; c < 4096; c += 1024) {
        unsigned long long key = 0ull;
        if (c < NCOLS) {
            double s = g_sum[c], q = g_sumsq[c];
            double var = (q - s * (s * (1.0 / 32768.0))) * (1.0 / 32767.0);
            float fv = (float)var;
            unsigned u = __float_as_uint(fv);
            u = (u & 0x80000000u) ? ~u : (u | 0x80000000u);
            key = ((unsigned long long)u << 32) |
                  (unsigned long long)(0xFFFFFFFFu - (unsigned)c);
        }
        keys[c] = key;
    }
    __syncthreads();
    for (int k = 2; k <= 4096; k <<= 1) {
        for (int j = k >> 1; j > 0; j >>= 1) {
            for (int i = tid; i < 4096; i += 1024) {
                int ixj = i ^ j;
                if (ixj > i) {
                    unsigned long long a = keys[i], bb = keys[ixj];
                    bool up = ((i & k) == 0);
                    bool sw = up ? (a < bb) : (a > bb);
                    if (sw) { keys[i] = bb; keys[ixj] = a; }
                }
            }
            __syncthreads();
        }
    }
    for (int r = tid; r < 1000; r += 1024)
        s_top[r] = (int)(0xFFFFFFFFu - (unsigned)(keys[r] & 0xFFFFFFFFull));
    __syncthreads();
    if (tid < 512) {
        int colid = s_top[feature_mask[tid]];
        s_selcol[tid] = colid;
        unsigned cls = (unsigned)(decode(colid) >> 24);
        s_key[tid] = (cls << 16) | (unsigned)tid;
    }
    __syncthreads();
    // bitonic ascending sort of 512 keys -> class-contiguous warps in gather
    for (int k = 2; k <= 512; k <<= 1) {
        for (int j = k >> 1; j > 0; j >>= 1) {
            if (tid < 512) {
                int ixj = tid ^ j;
                if (ixj > tid) {
                    unsigned a = s_key[tid], b = s_key[ixj];
                    bool up = ((tid & k) == 0);
                    if (up ? (a > b) : (a < b)) { s_key[tid] = b; s_key[ixj] = a; }
                }
            }
            __syncthreads();
        }
    }
    if (tid < 512) {
        unsigned key = s_key[tid];
        int j = (int)(key & 0xFFFFu);
        g_sel_j[tid] = j;
        g_sel_desc[tid] = decode(s_selcol[j]);
    }
}

// ---------------- gather: evaluate only selected columns -------------------
__global__ void __launch_bounds__(512, 2)
gather_kernel(const float* __restrict__ z_flat,
              const float* __restrict__ z_mean,
              const float* __restrict__ z_std,
              const float* __restrict__ x_poly_mean,
              const float* __restrict__ x_poly_std,
              const int* __restrict__ feature_mask,
              float* __restrict__ out) {
    __shared__ float s_zn[4][128];
    __shared__ float s_zp[4][32];
    __shared__ float s_d[4][120];
    __shared__ float s_out[4][512];
    const int tid = threadIdx.x;
    const int desc = g_sel_desc[tid];
    const int j = g_sel_j[tid];
    const int m = feature_mask[j];
    const float mj = x_poly_mean[m];
    const float sji = frcp(x_poly_std[m]);

    const int r_a = tid >> 7, c_a = tid & 127;
    const float zm = z_mean[c_a];
    const float zsi = frcp(z_std[c_a]);
    const int bp = tid % 120, br = tid / 120;
    int bi = 0, bj = 0;
    if (tid < 480) triu_pair(bp, 16, bi, bj);

    for (int g = blockIdx.x; g < NG4; g += GRID_P) {
        float z = z_flat[(g * 4 + r_a) * 128 + c_a];
        z = fminf(fmaxf(z, -1e6f), 1e6f);
        s_zn[r_a][c_a] = (z - zm) * zsi;
        if ((c_a & 7) < 2) s_zp[r_a][((c_a >> 3) << 1) | (c_a & 7)] = z;
        __syncthreads();
        if (tid < 480) {
            float dx = s_zp[br][2 * bi]     - s_zp[br][2 * bj];
            float dy = s_zp[br][2 * bi + 1] - s_zp[br][2 * bj + 1];
            dx -= 10.0f * rintf(dx * 0.1f);
            dy -= 10.0f * rintf(dy * 0.1f);
            s_d[br][bp] = fsqrt_a(dx * dx + dy * dy) + 1e-6f;
        }
        __syncthreads();
        #pragma unroll
        for (int r = 0; r < 4; r++) {
            float v = evalcol(desc, s_zn[r], s_d[r]);
            if (isnan(v)) v = 0.0f;
            else if (isinf(v)) v = (v > 0.0f) ? 1e9f : -1e9f;
            v = fminf(fmaxf(v, -1e12f), 1e12f);
            s_out[r][j] = (v - mj) * sji;
        }
        __syncthreads();
        {
            int r = tid >> 7, c4 = tid & 127;
            float4 w = *(const float4*)&s_out[r][c4 * 4];
            *(float4*)&out[(size_t)(g * 4 + r) * 512 + c4 * 4] = w;
        }
        __syncthreads();
    }
}

extern "C" void kernel_launch(void* const* d_in, const int* in_sizes, int n_in,
                              void* d_out, int out_size) {
    const float* z_flat      = (const float*)d_in[0];
    const float* z_mean      = (const float*)d_in[1];
    const float* z_std       = (const float*)d_in[2];
    const float* x_poly_mean = (const float*)d_in[3];
    const float* x_poly_std  = (const float*)d_in[4];
    const int*   feature_mask = (const int*)d_in[5];
    float* out = (float*)d_out;

    p1dist_kernel<<<GRID_P, 512>>>(z_flat);
    p1rest_kernel<<<GRID_P, 512>>>(z_flat, z_mean, z_std);
    reduce_kernel<<<8, 1024>>>();
    topk_kernel<<<1, 1024>>>(feature_mask);
    gather_kernel<<<GRID_P, 512>>>(z_flat, z_mean, z_std,
                                   x_poly_mean, x_poly_std, feature_mask, out);
}

// round 4
// speedup vs baseline: 2.4191x; 1.2954x over previous
#include <cuda_runtime.h>
#include <math.h>

#define NCOLS 3872
#define NROWS 32768
#define NG4   (NROWS / 4)
#define GRID_P 296
#define NDV 3360            // 120 pairs * 28 (14 sum + 14 sumsq)
#define NRV 2192            // non-dist columns

__device__ float  g_scr_d[GRID_P * NDV];
__device__ float  g_scr_r[GRID_P * NRV * 2];
__device__ double g_sum[NCOLS];
__device__ double g_sumsq[NCOLS];
__device__ unsigned long long g_key[4096];
__device__ int    g_top[1000];
__device__ int    g_sel_desc[512];
__device__ int    g_sel_j[512];

__device__ __forceinline__ float frcp(float x) {
    float r; asm("rcp.approx.f32 %0, %1;" : "=f"(r) : "f"(x)); return r;
}
__device__ __forceinline__ float fsqrt_a(float x) {
    float r; asm("sqrt.approx.f32 %0, %1;" : "=f"(r) : "f"(x)); return r;
}

__device__ __forceinline__ void triu_pair(int p, int n, int &i, int &j) {
    int ii = 0, rem = p, cnt = n - 1;
    while (rem >= cnt) { rem -= cnt; cnt--; ii++; }
    i = ii; j = ii + 1 + rem;
}

// Column descriptor: kind<<24 | a<<12 | b
__device__ __forceinline__ int decode(int c) {
    int kind, a, b = 0;
    if (c < 128)       { kind = 0; a = c; }
    else if (c < 1808) { int q = c - 128; kind = 16 + q / 120; a = q % 120; }
    else if (c < 1936) { kind = 1; a = c - 1808; }
    else if (c < 2064) { kind = 2; a = c - 1936; }
    else if (c < 2192) { kind = 3; a = c - 2064; }
    else if (c < 2320) { kind = 4; a = c - 2192; }
    else if (c < 2448) { kind = 5; a = c - 2320; }
    else if (c < 2464) { kind = 6; a = (c - 2448) * 8; }
    else if (c < 2912) {
        int idx = c - 2464; int n = idx / 28, pr = idx % 28;
        int i, j; triu_pair(pr, 8, i, j);
        kind = 7; a = n * 8 + i; b = n * 8 + j;
    } else {
        int idx = c - 2912; int pr = idx / 8, k = idx % 8;
        int i, j; triu_pair(pr, 16, i, j);
        kind = 7; a = i * 8 + k; b = j * 8 + k;
    }
    return (kind << 24) | (a << 12) | b;
}

__device__ __forceinline__ float evalrest(int desc, const float* __restrict__ zn) {
    int kind = desc >> 24;
    int a = (desc >> 12) & 0xFFF;
    int b = desc & 0xFFF;
    float v;
    switch (kind) {
        case 0: v = zn[a]; break;
        case 1: { float t = zn[a]; v = t * t; } break;
        case 2: v = __sinf(zn[a]); break;
        case 3: v = __cosf(zn[a]); break;
        case 4: v = __logf(fabsf(zn[a]) + 1e-3f); break;
        case 5: v = __expf(fminf(fmaxf(zn[a], -10.0f), 2.0f)); break;
        case 6: { float s = 0.0f;
                  #pragma unroll
                  for (int k = 4; k < 8; k++) { float t = zn[a + k]; s += t * t; }
                  v = s; } break;
        default: v = zn[a] * zn[b]; break;
    }
    return v;
}

__device__ __forceinline__ float evalcol(int desc, const float* __restrict__ zn,
                                         const float* __restrict__ dv) {
    int kind = desc >> 24;
    if (kind >= 16) {
        int a = (desc >> 12) & 0xFFF;
        float dd = dv[a];
        float v;
        switch (kind - 16) {
            case 0: v = dd; break;
            case 1: v = frcp(dd + 1e-3f); break;
            case 2: v = frcp(dd * dd + 1e-3f); break;
            case 3: { float d2 = dd * dd; v = frcp(d2 * dd + 1e-3f); } break;
            case 4: { float d2 = dd * dd; v = frcp(d2 * d2 + 1e-3f); } break;
            case 5: { float d2 = dd * dd; v = frcp(d2 * d2 * dd + 1e-3f); } break;
            case 6: { float d2 = dd * dd; float d4 = d2 * d2; v = frcp(d4 * d2 + 1e-3f); } break;
            case 7: { float d2 = dd * dd; float d4 = d2 * d2; v = frcp(d4 * d4 + 1e-3f); } break;
            case 8: { float d2 = dd * dd; float d4 = d2 * d2; v = frcp(d4 * d4 * d2 + 1e-3f); } break;
            case 9: { float d2 = dd * dd; float d4 = d2 * d2; v = frcp(d4 * d4 * d4 + 1e-3f); } break;
            case 10:{ float d2 = dd * dd; float d4 = d2 * d2; float d8 = d4 * d4;
                      v = frcp(d8 * d4 * d2 + 1e-3f); } break;
            case 11: v = __expf(-dd); break;
            case 12: v = __expf(-dd) * frcp(dd + 1e-3f); break;
            default: v = __logf(dd + 1e-3f); break;
        }
        return fminf(fmaxf(v, -1e6f), 1e6f);
    }
    return evalrest(desc, zn);
}

// ---------------- pass 1a: distance-derived columns ------------------------
__global__ void __launch_bounds__(512, 2)
p1dist_kernel(const float* __restrict__ z_flat) {
    __shared__ float s_zp[4][32];
    __shared__ float s_red[NDV];
    const int tid = threadIdx.x;
    const int r_a = tid >> 7, c_a = tid & 127;
    const int bp = tid % 120, br = tid / 120;
    int bi = 0, bj = 0;
    if (tid < 480) triu_pair(bp, 16, bi, bj);

    float acc[28];
    #pragma unroll
    for (int k = 0; k < 28; k++) acc[k] = 0.f;

    float z = z_flat[(blockIdx.x * 4 + r_a) * 128 + c_a];
    for (int g = blockIdx.x; g < NG4; g += GRID_P) {
        z = fminf(fmaxf(z, -1e6f), 1e6f);
        if ((c_a & 7) < 2) s_zp[r_a][((c_a >> 3) << 1) | (c_a & 7)] = z;
        __syncthreads();
        int gn = g + GRID_P;
        float z_next = 0.f;
        if (gn < NG4) z_next = z_flat[(gn * 4 + r_a) * 128 + c_a];
        if (tid < 480) {
            float dx = s_zp[br][2 * bi]     - s_zp[br][2 * bj];
            float dy = s_zp[br][2 * bi + 1] - s_zp[br][2 * bj + 1];
            dx -= 10.0f * rintf(dx * 0.1f);
            dy -= 10.0f * rintf(dy * 0.1f);
            float d = fsqrt_a(dx * dx + dy * dy) + 1e-6f;
            float dpe = d + 1e-3f;
            float r1 = frcp(dpe);
            float d2 = d * d, d3 = d2 * d, d4 = d2 * d2, d6 = d3 * d3, d8 = d4 * d4;
            float v[14];
            v[0] = d;
            v[1] = r1;
            v[2] = frcp(d2 + 1e-3f);
            v[3] = frcp(d3 + 1e-3f);
            v[4] = frcp(d4 + 1e-3f);
            v[5] = frcp(d4 * d + 1e-3f);
            v[6] = frcp(d6 + 1e-3f);
            v[7] = frcp(d8 + 1e-3f);
            v[8] = frcp(d8 * d2 + 1e-3f);
            v[9] = frcp(d6 * d6 + 1e-3f);
            v[10] = frcp(d8 * d6 + 1e-3f);
            float e = __expf(-d);
            v[11] = e;
            v[12] = e * r1;
            v[13] = __logf(dpe);
            #pragma unroll
            for (int k = 0; k < 14; k++) {
                acc[k] += v[k];
                acc[14 + k] = fmaf(v[k], v[k], acc[14 + k]);
            }
        }
        __syncthreads();
        z = z_next;
    }
    if (tid < 480 && br == 0) {
        #pragma unroll
        for (int k = 0; k < 28; k++) s_red[bp * 28 + k] = acc[k];
    }
    __syncthreads();
    for (int s = 1; s < 4; s++) {
        if (tid < 480 && br == s) {
            #pragma unroll
            for (int k = 0; k < 28; k++) s_red[bp * 28 + k] += acc[k];
        }
        __syncthreads();
    }
    for (int v = tid; v < NDV; v += 512)
        g_scr_d[blockIdx.x * NDV + v] = s_red[v];
}

// ---------------- pass 1b: non-distance columns ----------------------------
__global__ void __launch_bounds__(512, 2)
p1rest_kernel(const float* __restrict__ z_flat,
              const float* __restrict__ z_mean,
              const float* __restrict__ z_std) {
    __shared__ float s_zn[4][128];
    const int tid = threadIdx.x;
    const int r_a = tid >> 7, c_a = tid & 127;
    const float zm = z_mean[c_a];
    const float zsi = frcp(z_std[c_a]);

    int desc[5]; bool val[5];
    #pragma unroll
    for (int k = 0; k < 5; k++) {
        int i = tid + k * 512;
        val[k] = (i < NRV);
        int col = (i < 128) ? i : i + 1680;
        desc[k] = val[k] ? decode(col) : 0;
    }
    float fs[5], fq[5];
    #pragma unroll
    for (int k = 0; k < 5; k++) { fs[k] = 0.f; fq[k] = 0.f; }

    float z = z_flat[(blockIdx.x * 4 + r_a) * 128 + c_a];
    for (int g = blockIdx.x; g < NG4; g += GRID_P) {
        z = fminf(fmaxf(z, -1e6f), 1e6f);
        s_zn[r_a][c_a] = (z - zm) * zsi;
        __syncthreads();
        int gn = g + GRID_P;
        float z_next = 0.f;
        if (gn < NG4) z_next = z_flat[(gn * 4 + r_a) * 128 + c_a];
        #pragma unroll
        for (int r = 0; r < 4; r++) {
            const float* zn = s_zn[r];
            #pragma unroll
            for (int k = 0; k < 5; k++) {
                if (val[k]) {
                    float v = evalrest(desc[k], zn);
                    fs[k] += v;
                    fq[k] = fmaf(v, v, fq[k]);
                }
            }
        }
        __syncthreads();
        z = z_next;
    }
    #pragma unroll
    for (int k = 0; k < 5; k++) {
        int i = tid + k * 512;
        if (val[k]) {
            g_scr_r[blockIdx.x * (2 * NRV) + i] = fs[k];
            g_scr_r[blockIdx.x * (2 * NRV) + NRV + i] = fq[k];
        }
    }
}

// ---------------- reduce partials into f64 sums ----------------------------
__global__ void reduce_kernel() {
    int v = blockIdx.x * blockDim.x + threadIdx.x;
    if (v < NDV) {
        double s = 0.0;
        for (int b = 0; b < GRID_P; b++) s += (double)g_scr_d[b * NDV + v];
        int pair = v / 28, k = v % 28;
        int col = 128 + (k % 14) * 120 + pair;
        if (k < 14) g_sum[col] = s; else g_sumsq[col] = s;
    } else if (v < NDV + 2 * NRV) {
        int i = v - NDV;
        double s = 0.0;
        for (int b = 0; b < GRID_P; b++) s += (double)g_scr_r[b * 2 * NRV + i];
        int ii = (i < NRV) ? i : i - NRV;
        int col = (ii < 128) ? ii : ii + 1680;
        if (i < NRV) g_sum[col] = s; else g_sumsq[col] = s;
    }
}

// ---------------- keys: f64 variance -> monotone u64 key -------------------
__global__ void keys_kernel() {
    int c = blockIdx.x * blockDim.x + threadIdx.x;
    if (c >= 4096) return;
    unsigned long long key = 0ull;
    if (c < NCOLS) {
        double s = g_sum[c], q = g_sumsq[c];
        double var = (q - s * (s * (1.0 / 32768.0))) * (1.0 / 32767.0);
        float fv = (float)var;
        unsigned u = __float_as_uint(fv);
        u = (u & 0x80000000u) ? ~u : (u | 0x80000000u);
        key = ((unsigned long long)u << 32) |
              (unsigned long long)(0xFFFFFFFFu - (unsigned)c);
    }
    g_key[c] = key;
}

// ---------------- rank-by-counting: exact top-1000 order -------------------
__global__ void __launch_bounds__(128, 8)
rank_kernel() {
    __shared__ unsigned long long sk[4096];
    const int tid = threadIdx.x;
    for (int i = tid; i < 4096; i += 128) sk[i] = g_key[i];
    __syncthreads();
    int c = blockIdx.x * 128 + tid;
    unsigned long long mykey = sk[c];
    int r = 0;
    #pragma unroll 8
    for (int i = 0; i < 4096; i++) r += (sk[i] > mykey);
    if (c < NCOLS && r < 1000) g_top[r] = c;
}

// ---------------- selection + class sort ------------------------------------
__global__ void __launch_bounds__(512, 1)
sel_kernel(const int* __restrict__ feature_mask) {
    __shared__ int s_selcol[512];
    __shared__ unsigned s_key[512];
    const int tid = threadIdx.x;
    int colid = g_top[feature_mask[tid]];
    s_selcol[tid] = colid;
    unsigned cls = (unsigned)(decode(colid) >> 24);
    s_key[tid] = (cls << 16) | (unsigned)tid;
    __syncthreads();
    for (int k = 2; k <= 512; k <<= 1) {
        for (int j = k >> 1; j > 0; j >>= 1) {
            int ixj = tid ^ j;
            if (ixj > tid) {
                unsigned a = s_key[tid], b = s_key[ixj];
                bool up = ((tid & k) == 0);
                if (up ? (a > b) : (a < b)) { s_key[tid] = b; s_key[ixj] = a; }
            }
            __syncthreads();
        }
    }
    unsigned key = s_key[tid];
    int j = (int)(key & 0xFFFFu);
    g_sel_j[tid] = j;
    g_sel_desc[tid] = decode(s_selcol[j]);
}

// ---------------- gather ----------------------------------------------------
__global__ void __launch_bounds__(512, 2)
gather_kernel(const float* __restrict__ z_flat,
              const float* __restrict__ z_mean,
              const float* __restrict__ z_std,
              const float* __restrict__ x_poly_mean,
              const float* __restrict__ x_poly_std,
              const int* __restrict__ feature_mask,
              float* __restrict__ out) {
    __shared__ float s_zn[4][128];
    __shared__ float s_zp[4][32];
    __shared__ float s_d[4][120];
    __shared__ float s_out[4][512];
    const int tid = threadIdx.x;
    const int desc = g_sel_desc[tid];
    const int j = g_sel_j[tid];
    const int m = feature_mask[j];
    const float mj = x_poly_mean[m];
    const float sji = frcp(x_poly_std[m]);

    const int r_a = tid >> 7, c_a = tid & 127;
    const float zm = z_mean[c_a];
    const float zsi = frcp(z_std[c_a]);
    const int bp = tid % 120, br = tid / 120;
    int bi = 0, bj = 0;
    if (tid < 480) triu_pair(bp, 16, bi, bj);

    float z = z_flat[(blockIdx.x * 4 + r_a) * 128 + c_a];
    for (int g = blockIdx.x; g < NG4; g += GRID_P) {
        z = fminf(fmaxf(z, -1e6f), 1e6f);
        s_zn[r_a][c_a] = (z - zm) * zsi;
        if ((c_a & 7) < 2) s_zp[r_a][((c_a >> 3) << 1) | (c_a & 7)] = z;
        __syncthreads();
        int gn = g + GRID_P;
        float z_next = 0.f;
        if (gn < NG4) z_next = z_flat[(gn * 4 + r_a) * 128 + c_a];
        if (tid < 480) {
            float dx = s_zp[br][2 * bi]     - s_zp[br][2 * bj];
            float dy = s_zp[br][2 * bi + 1] - s_zp[br][2 * bj + 1];
            dx -= 10.0f * rintf(dx * 0.1f);
            dy -= 10.0f * rintf(dy * 0.1f);
            s_d[br][bp] = fsqrt_a(dx * dx + dy * dy) + 1e-6f;
        }
        __syncthreads();
        #pragma unroll
        for (int r = 0; r < 4; r++) {
            float v = evalcol(desc, s_zn[r], s_d[r]);
            if (isnan(v)) v = 0.0f;
            else if (isinf(v)) v = (v > 0.0f) ? 1e9f : -1e9f;
            v = fminf(fmaxf(v, -1e12f), 1e12f);
            s_out[r][j] = (v - mj) * sji;
        }
        __syncthreads();
        {
            int r = tid >> 7, c4 = tid & 127;
            float4 w = *(const float4*)&s_out[r][c4 * 4];
            *(float4*)&out[(size_t)(g * 4 + r) * 512 + c4 * 4] = w;
        }
        __syncthreads();
        z = z_next;
    }
}

extern "C" void kernel_launch(void* const* d_in, const int* in_sizes, int n_in,
                              void* d_out, int out_size) {
    const float* z_flat      = (const float*)d_in[0];
    const float* z_mean      = (const float*)d_in[1];
    const float* z_std       = (const float*)d_in[2];
    const float* x_poly_mean = (const float*)d_in[3];
    const float* x_poly_std  = (const float*)d_in[4];
    const int*   feature_mask = (const int*)d_in[5];
    float* out = (float*)d_out;

    p1dist_kernel<<<GRID_P, 512>>>(z_flat);
    p1rest_kernel<<<GRID_P, 512>>>(z_flat, z_mean, z_std);
    reduce_kernel<<<8, 1024>>>();
    keys_kernel<<<4, 1024>>>();
    rank_kernel<<<32, 128>>>();
    sel_kernel<<<1, 512>>>(feature_mask);
    gather_kernel<<<GRID_P, 512>>>(z_flat, z_mean, z_std,
                                   x_poly_mean, x_poly_std, feature_mask, out);
}

// round 5
// speedup vs baseline: 3.6181x; 1.4956x over previous
#include <cuda_runtime.h>
#include <math.h>

#define NCOLS 3872
#define NROWS 32768
#define NG8   (NROWS / 8)
#define GRID_P 296
#define NDV 3360            // 120 pairs * 28 (14 sum + 14 sumsq)
#define NRV 2192            // non-dist columns
#define NVAL (NDV + 2 * NRV)   // 7744
#define CHUNK 37               // 296 / 8

__device__ float  g_scr_d[GRID_P * NDV];
__device__ float  g_scr_r[GRID_P * NRV * 2];
__device__ double g_part[8 * NVAL];
__device__ int    g_top[1000];
__device__ int    g_sel_desc[512];
__device__ int    g_sel_j[512];

__device__ __forceinline__ float frcp(float x) {
    float r; asm("rcp.approx.f32 %0, %1;" : "=f"(r) : "f"(x)); return r;
}
__device__ __forceinline__ float fsqrt_a(float x) {
    float r; asm("sqrt.approx.f32 %0, %1;" : "=f"(r) : "f"(x)); return r;
}

__device__ __forceinline__ void triu_pair(int p, int n, int &i, int &j) {
    int ii = 0, rem = p, cnt = n - 1;
    while (rem >= cnt) { rem -= cnt; cnt--; ii++; }
    i = ii; j = ii + 1 + rem;
}

// Column descriptor: kind<<24 | a<<12 | b
__device__ __forceinline__ int decode(int c) {
    int kind, a, b = 0;
    if (c < 128)       { kind = 0; a = c; }
    else if (c < 1808) { int q = c - 128; kind = 16 + q / 120; a = q % 120; }
    else if (c < 1936) { kind = 1; a = c - 1808; }
    else if (c < 2064) { kind = 2; a = c - 1936; }
    else if (c < 2192) { kind = 3; a = c - 2064; }
    else if (c < 2320) { kind = 4; a = c - 2192; }
    else if (c < 2448) { kind = 5; a = c - 2320; }
    else if (c < 2464) { kind = 6; a = (c - 2448) * 8; }
    else if (c < 2912) {
        int idx = c - 2464; int n = idx / 28, pr = idx % 28;
        int i, j; triu_pair(pr, 8, i, j);
        kind = 7; a = n * 8 + i; b = n * 8 + j;
    } else {
        int idx = c - 2912; int pr = idx / 8, k = idx % 8;
        int i, j; triu_pair(pr, 16, i, j);
        kind = 7; a = i * 8 + k; b = j * 8 + k;
    }
    return (kind << 24) | (a << 12) | b;
}

__device__ __forceinline__ float evalrest(int desc, const float* __restrict__ zn) {
    int kind = desc >> 24;
    int a = (desc >> 12) & 0xFFF;
    int b = desc & 0xFFF;
    float v;
    switch (kind) {
        case 0: v = zn[a]; break;
        case 1: { float t = zn[a]; v = t * t; } break;
        case 2: v = __sinf(zn[a]); break;
        case 3: v = __cosf(zn[a]); break;
        case 4: v = __logf(fabsf(zn[a]) + 1e-3f); break;
        case 5: v = __expf(fminf(fmaxf(zn[a], -10.0f), 2.0f)); break;
        case 6: { float s = 0.0f;
                  #pragma unroll
                  for (int k = 4; k < 8; k++) { float t = zn[a + k]; s += t * t; }
                  v = s; } break;
        default: v = zn[a] * zn[b]; break;
    }
    return v;
}

__device__ __forceinline__ float evalcol(int desc, const float* __restrict__ zn,
                                         const float* __restrict__ dv) {
    int kind = desc >> 24;
    if (kind >= 16) {
        int a = (desc >> 12) & 0xFFF;
        float dd = dv[a];
        float v;
        switch (kind - 16) {
            case 0: v = dd; break;
            case 1: v = frcp(dd + 1e-3f); break;
            case 2: v = frcp(dd * dd + 1e-3f); break;
            case 3: { float d2 = dd * dd; v = frcp(d2 * dd + 1e-3f); } break;
            case 4: { float d2 = dd * dd; v = frcp(d2 * d2 + 1e-3f); } break;
            case 5: { float d2 = dd * dd; v = frcp(d2 * d2 * dd + 1e-3f); } break;
            case 6: { float d2 = dd * dd; float d4 = d2 * d2; v = frcp(d4 * d2 + 1e-3f); } break;
            case 7: { float d2 = dd * dd; float d4 = d2 * d2; v = frcp(d4 * d4 + 1e-3f); } break;
            case 8: { float d2 = dd * dd; float d4 = d2 * d2; v = frcp(d4 * d4 * d2 + 1e-3f); } break;
            case 9: { float d2 = dd * dd; float d4 = d2 * d2; v = frcp(d4 * d4 * d4 + 1e-3f); } break;
            case 10:{ float d2 = dd * dd; float d4 = d2 * d2; float d8 = d4 * d4;
                      v = frcp(d8 * d4 * d2 + 1e-3f); } break;
            case 11: v = __expf(-dd); break;
            case 12: v = __expf(-dd) * frcp(dd + 1e-3f); break;
            default: v = __logf(dd + 1e-3f); break;
        }
        return fminf(fmaxf(v, -1e6f), 1e6f);
    }
    return evalrest(desc, zn);
}

// distance power chain: accumulate 14 values + squares for distance d
__device__ __forceinline__ void dchain(float d, float acc[28]) {
    float dpe = d + 1e-3f;
    float r1 = frcp(dpe);
    float d2 = d * d, d3 = d2 * d, d4 = d2 * d2, d6 = d3 * d3, d8 = d4 * d4;
    float v[14];
    v[0] = d;
    v[1] = r1;
    v[2] = frcp(d2 + 1e-3f);
    v[3] = frcp(d3 + 1e-3f);
    v[4] = frcp(d4 + 1e-3f);
    v[5] = frcp(d4 * d + 1e-3f);
    v[6] = frcp(d6 + 1e-3f);
    v[7] = frcp(d8 + 1e-3f);
    v[8] = frcp(d8 * d2 + 1e-3f);
    v[9] = frcp(d6 * d6 + 1e-3f);
    v[10] = frcp(d8 * d6 + 1e-3f);
    float e = __expf(-d);
    v[11] = e;
    v[12] = e * r1;
    v[13] = __logf(dpe);
    #pragma unroll
    for (int k = 0; k < 14; k++) {
        acc[k] += v[k];
        acc[14 + k] = fmaf(v[k], v[k], acc[14 + k]);
    }
}

__device__ __forceinline__ float pbc_dist(const float* zp, int bi, int bj) {
    float dx = zp[2 * bi]     - zp[2 * bj];
    float dy = zp[2 * bi + 1] - zp[2 * bj + 1];
    dx -= 10.0f * rintf(dx * 0.1f);
    dy -= 10.0f * rintf(dy * 0.1f);
    return fsqrt_a(dx * dx + dy * dy) + 1e-6f;
}

// ---------------- pass 1a: distance-derived columns ------------------------
__global__ void __launch_bounds__(512, 2)
p1dist_kernel(const float* __restrict__ z_flat) {
    __shared__ float s_zp[8][32];
    __shared__ float s_red[NDV];
    const int tid = threadIdx.x;
    const int r0 = tid >> 7, c0 = tid & 127;
    const int bp = tid % 120, br = tid / 120;
    int bi = 0, bj = 0;
    if (tid < 480) triu_pair(bp, 16, bi, bj);
    const bool zkeep = ((c0 & 7) < 2);
    const int zslot = ((c0 >> 3) << 1) | (c0 & 7);

    float acc[28];
    #pragma unroll
    for (int k = 0; k < 28; k++) acc[k] = 0.f;

    float za = z_flat[(blockIdx.x * 8 + r0) * 128 + c0];
    float zb = z_flat[(blockIdx.x * 8 + r0 + 4) * 128 + c0];
    for (int g = blockIdx.x; g < NG8; g += GRID_P) {
        if (zkeep) {
            s_zp[r0][zslot]     = fminf(fmaxf(za, -1e6f), 1e6f);
            s_zp[r0 + 4][zslot] = fminf(fmaxf(zb, -1e6f), 1e6f);
        }
        __syncthreads();
        int gn = g + GRID_P;
        float za_n = 0.f, zb_n = 0.f;
        if (gn < NG8) {
            za_n = z_flat[(gn * 8 + r0) * 128 + c0];
            zb_n = z_flat[(gn * 8 + r0 + 4) * 128 + c0];
        }
        if (tid < 480) {
            dchain(pbc_dist(s_zp[br], bi, bj), acc);
            dchain(pbc_dist(s_zp[br + 4], bi, bj), acc);
        }
        __syncthreads();
        za = za_n; zb = zb_n;
    }
    if (tid < 480 && br == 0) {
        #pragma unroll
        for (int k = 0; k < 28; k++) s_red[bp * 28 + k] = acc[k];
    }
    __syncthreads();
    for (int s = 1; s < 4; s++) {
        if (tid < 480 && br == s) {
            #pragma unroll
            for (int k = 0; k < 28; k++) s_red[bp * 28 + k] += acc[k];
        }
        __syncthreads();
    }
    for (int v = tid; v < NDV; v += 512)
        g_scr_d[blockIdx.x * NDV + v] = s_red[v];
}

// ---------------- pass 1b: non-distance columns ----------------------------
__global__ void __launch_bounds__(512, 2)
p1rest_kernel(const float* __restrict__ z_flat,
              const float* __restrict__ z_mean,
              const float* __restrict__ z_std) {
    __shared__ float s_zn[8][128];
    const int tid = threadIdx.x;
    const int r0 = tid >> 7, c0 = tid & 127;
    const float zma = z_mean[c0];
    const float zsia = frcp(z_std[c0]);

    int desc[5]; bool val[5];
    #pragma unroll
    for (int k = 0; k < 5; k++) {
        int i = tid + k * 512;
        val[k] = (i < NRV);
        int col = (i < 128) ? i : i + 1680;
        desc[k] = val[k] ? decode(col) : 0;
    }
    float fs[5], fq[5];
    #pragma unroll
    for (int k = 0; k < 5; k++) { fs[k] = 0.f; fq[k] = 0.f; }

    float za = z_flat[(blockIdx.x * 8 + r0) * 128 + c0];
    float zb = z_flat[(blockIdx.x * 8 + r0 + 4) * 128 + c0];
    for (int g = blockIdx.x; g < NG8; g += GRID_P) {
        s_zn[r0][c0]     = (fminf(fmaxf(za, -1e6f), 1e6f) - zma) * zsia;
        s_zn[r0 + 4][c0] = (fminf(fmaxf(zb, -1e6f), 1e6f) - zma) * zsia;
        __syncthreads();
        int gn = g + GRID_P;
        float za_n = 0.f, zb_n = 0.f;
        if (gn < NG8) {
            za_n = z_flat[(gn * 8 + r0) * 128 + c0];
            zb_n = z_flat[(gn * 8 + r0 + 4) * 128 + c0];
        }
        #pragma unroll
        for (int r = 0; r < 8; r++) {
            const float* zn = s_zn[r];
            #pragma unroll
            for (int k = 0; k < 5; k++) {
                if (val[k]) {
                    float v = evalrest(desc[k], zn);
                    fs[k] += v;
                    fq[k] = fmaf(v, v, fq[k]);
                }
            }
        }
        __syncthreads();
        za = za_n; zb = zb_n;
    }
    #pragma unroll
    for (int k = 0; k < 5; k++) {
        int i = tid + k * 512;
        if (val[k]) {
            g_scr_r[blockIdx.x * (2 * NRV) + i] = fs[k];
            g_scr_r[blockIdx.x * (2 * NRV) + NRV + i] = fq[k];
        }
    }
}

// ---------------- reduce stage 1: 296 partials -> 8 f64 chunks -------------
__global__ void __launch_bounds__(1024, 2)
reduce1_kernel() {
    int t = blockIdx.x * 1024 + threadIdx.x;
    int chunk = t / NVAL;
    int v = t - chunk * NVAL;
    if (chunk >= 8) return;
    double s = 0.0;
    int b0 = chunk * CHUNK;
    if (v < NDV) {
        #pragma unroll 4
        for (int b = b0; b < b0 + CHUNK; b++) s += (double)g_scr_d[b * NDV + v];
    } else {
        int i = v - NDV;
        #pragma unroll 4
        for (int b = b0; b < b0 + CHUNK; b++) s += (double)g_scr_r[b * (2 * NRV) + i];
    }
    g_part[chunk * NVAL + v] = s;
}

// ---------------- rank: fold partials, build keys, rank-by-count -----------
__global__ void __launch_bounds__(128, 8)
rank_kernel() {
    __shared__ unsigned long long sk[4096];
    const int tid = threadIdx.x;
    for (int c = tid; c < 4096; c += 128) {
        unsigned long long key = 0ull;
        if (c < NCOLS) {
            int vs, vq;
            if (c < 128)        { vs = NDV + c; vq = NDV + NRV + c; }
            else if (c < 1808)  { int q = c - 128; int kk = q / 120; int pr = q % 120;
                                  vs = pr * 28 + kk; vq = vs + 14; }
            else                { int i = c - 1680; vs = NDV + i; vq = NDV + NRV + i; }
            double s = 0.0, qq = 0.0;
            #pragma unroll
            for (int ch = 0; ch < 8; ch++) {
                s  += g_part[ch * NVAL + vs];
                qq += g_part[ch * NVAL + vq];
            }
            double var = (qq - s * (s * (1.0 / 32768.0))) * (1.0 / 32767.0);
            float fv = (float)var;
            unsigned u = __float_as_uint(fv);
            u = (u & 0x80000000u) ? ~u : (u | 0x80000000u);
            key = ((unsigned long long)u << 32) |
                  (unsigned long long)(0xFFFFFFFFu - (unsigned)c);
        }
        sk[c] = key;
    }
    __syncthreads();
    int c = blockIdx.x * 128 + tid;
    unsigned long long mykey = sk[c];
    int r = 0;
    #pragma unroll 8
    for (int i = 0; i < 4096; i++) r += (sk[i] > mykey);
    if (c < NCOLS && r < 1000) g_top[r] = c;
}

// ---------------- selection + class sort ------------------------------------
__global__ void __launch_bounds__(512, 1)
sel_kernel(const int* __restrict__ feature_mask) {
    __shared__ int s_selcol[512];
    __shared__ unsigned s_key[512];
    const int tid = threadIdx.x;
    int colid = g_top[feature_mask[tid]];
    s_selcol[tid] = colid;
    unsigned cls = (unsigned)(decode(colid) >> 24);
    s_key[tid] = (cls << 16) | (unsigned)tid;
    __syncthreads();
    for (int k = 2; k <= 512; k <<= 1) {
        for (int j = k >> 1; j > 0; j >>= 1) {
            int ixj = tid ^ j;
            if (ixj > tid) {
                unsigned a = s_key[tid], b = s_key[ixj];
                bool up = ((tid & k) == 0);
                if (up ? (a > b) : (a < b)) { s_key[tid] = b; s_key[ixj] = a; }
            }
            __syncthreads();
        }
    }
    unsigned key = s_key[tid];
    int j = (int)(key & 0xFFFFu);
    g_sel_j[tid] = j;
    g_sel_desc[tid] = decode(s_selcol[j]);
}

// ---------------- gather ----------------------------------------------------
__global__ void __launch_bounds__(512, 2)
gather_kernel(const float* __restrict__ z_flat,
              const float* __restrict__ z_mean,
              const float* __restrict__ z_std,
              const float* __restrict__ x_poly_mean,
              const float* __restrict__ x_poly_std,
              const int* __restrict__ feature_mask,
              float* __restrict__ out) {
    __shared__ float s_zn[8][128];
    __shared__ float s_zp[8][32];
    __shared__ float s_d[8][120];
    __shared__ float s_out[8][512];
    const int tid = threadIdx.x;
    const int desc = g_sel_desc[tid];
    const int j = g_sel_j[tid];
    const int m = feature_mask[j];
    const float mj = x_poly_mean[m];
    const float sji = frcp(x_poly_std[m]);

    const int r0 = tid >> 7, c0 = tid & 127;
    const float zma = z_mean[c0];
    const float zsia = frcp(z_std[c0]);
    const int bp = tid % 120, br = tid / 120;
    int bi = 0, bj = 0;
    if (tid < 480) triu_pair(bp, 16, bi, bj);
    const bool zkeep = ((c0 & 7) < 2);
    const int zslot = ((c0 >> 3) << 1) | (c0 & 7);

    float za = z_flat[(blockIdx.x * 8 + r0) * 128 + c0];
    float zb = z_flat[(blockIdx.x * 8 + r0 + 4) * 128 + c0];
    for (int g = blockIdx.x; g < NG8; g += GRID_P) {
        float zac = fminf(fmaxf(za, -1e6f), 1e6f);
        float zbc = fminf(fmaxf(zb, -1e6f), 1e6f);
        s_zn[r0][c0]     = (zac - zma) * zsia;
        s_zn[r0 + 4][c0] = (zbc - zma) * zsia;
        if (zkeep) { s_zp[r0][zslot] = zac; s_zp[r0 + 4][zslot] = zbc; }
        __syncthreads();
        int gn = g + GRID_P;
        float za_n = 0.f, zb_n = 0.f;
        if (gn < NG8) {
            za_n = z_flat[(gn * 8 + r0) * 128 + c0];
            zb_n = z_flat[(gn * 8 + r0 + 4) * 128 + c0];
        }
        if (tid < 480) {
            s_d[br][bp]     = pbc_dist(s_zp[br], bi, bj);
            s_d[br + 4][bp] = pbc_dist(s_zp[br + 4], bi, bj);
        }
        __syncthreads();
        #pragma unroll
        for (int r = 0; r < 8; r++) {
            float v = evalcol(desc, s_zn[r], s_d[r]);
            if (isnan(v)) v = 0.0f;
            else if (isinf(v)) v = (v > 0.0f) ? 1e9f : -1e9f;
            v = fminf(fmaxf(v, -1e12f), 1e12f);
            s_out[r][j] = (v - mj) * sji;
        }
        __syncthreads();
        #pragma unroll
        for (int w = 0; w < 2; w++) {
            int f = tid + w * 512;            // float4 index within 8x512 tile
            int r = f >> 7, c4 = f & 127;
            float4 wv = *(const float4*)&s_out[r][c4 * 4];
            *(float4*)&out[(size_t)(g * 8 + r) * 512 + c4 * 4] = wv;
        }
        za = za_n; zb = zb_n;
    }
}

extern "C" void kernel_launch(void* const* d_in, const int* in_sizes, int n_in,
                              void* d_out, int out_size) {
    const float* z_flat      = (const float*)d_in[0];
    const float* z_mean      = (const float*)d_in[1];
    const float* z_std       = (const float*)d_in[2];
    const float* x_poly_mean = (const float*)d_in[3];
    const float* x_poly_std  = (const float*)d_in[4];
    const int*   feature_mask = (const int*)d_in[5];
    float* out = (float*)d_out;

    p1dist_kernel<<<GRID_P, 512>>>(z_flat);
    p1rest_kernel<<<GRID_P, 512>>>(z_flat, z_mean, z_std);
    reduce1_kernel<<<(8 * NVAL + 1023) / 1024, 1024>>>();
    rank_kernel<<<32, 128>>>();
    sel_kernel<<<1, 512>>>(feature_mask);
    gather_kernel<<<GRID_P, 512>>>(z_flat, z_mean, z_std,
                                   x_poly_mean, x_poly_std, feature_mask, out);
}

// round 6
// speedup vs baseline: 4.3382x; 1.1990x over previous
#include <cuda_runtime.h>
#include <math.h>

#define NCOLS 3872
#define NROWS 32768
#define NG8   (NROWS / 8)
#define GRID_P 296
#define NDV 3360            // 120 pairs * 28 (14 sum + 14 sumsq)
#define NRV 2192            // non-dist columns
#define NVAL (NDV + 2 * NRV)   // 7744
#define CHUNK 37               // 296 / 8

__device__ float  g_scr_d[GRID_P * NDV];
__device__ float  g_scr_r[GRID_P * NRV * 2];
__device__ double g_part[8 * NVAL];
__device__ unsigned long long g_key[4096];
__device__ int    g_top[1000];
__device__ int    g_sel_desc[512];
__device__ int    g_sel_j[512];

__device__ __forceinline__ float frcp(float x) {
    float r; asm("rcp.approx.f32 %0, %1;" : "=f"(r) : "f"(x)); return r;
}
__device__ __forceinline__ float fsqrt_a(float x) {
    float r; asm("sqrt.approx.f32 %0, %1;" : "=f"(r) : "f"(x)); return r;
}

__device__ __forceinline__ void triu_pair(int p, int n, int &i, int &j) {
    int ii = 0, rem = p, cnt = n - 1;
    while (rem >= cnt) { rem -= cnt; cnt--; ii++; }
    i = ii; j = ii + 1 + rem;
}

// Column descriptor: kind<<24 | a<<12 | b
__device__ __forceinline__ int decode(int c) {
    int kind, a, b = 0;
    if (c < 128)       { kind = 0; a = c; }
    else if (c < 1808) { int q = c - 128; kind = 16 + q / 120; a = q % 120; }
    else if (c < 1936) { kind = 1; a = c - 1808; }
    else if (c < 2064) { kind = 2; a = c - 1936; }
    else if (c < 2192) { kind = 3; a = c - 2064; }
    else if (c < 2320) { kind = 4; a = c - 2192; }
    else if (c < 2448) { kind = 5; a = c - 2320; }
    else if (c < 2464) { kind = 6; a = (c - 2448) * 8; }
    else if (c < 2912) {
        int idx = c - 2464; int n = idx / 28, pr = idx % 28;
        int i, j; triu_pair(pr, 8, i, j);
        kind = 7; a = n * 8 + i; b = n * 8 + j;
    } else {
        int idx = c - 2912; int pr = idx / 8, k = idx % 8;
        int i, j; triu_pair(pr, 16, i, j);
        kind = 7; a = i * 8 + k; b = j * 8 + k;
    }
    return (kind << 24) | (a << 12) | b;
}

__device__ __forceinline__ float evalrest(int desc, const float* __restrict__ zn) {
    int kind = desc >> 24;
    int a = (desc >> 12) & 0xFFF;
    int b = desc & 0xFFF;
    float v;
    switch (kind) {
        case 0: v = zn[a]; break;
        case 1: { float t = zn[a]; v = t * t; } break;
        case 2: v = __sinf(zn[a]); break;
        case 3: v = __cosf(zn[a]); break;
        case 4: v = __logf(fabsf(zn[a]) + 1e-3f); break;
        case 5: v = __expf(fminf(fmaxf(zn[a], -10.0f), 2.0f)); break;
        case 6: { float s = 0.0f;
                  #pragma unroll
                  for (int k = 4; k < 8; k++) { float t = zn[a + k]; s += t * t; }
                  v = s; } break;
        default: v = zn[a] * zn[b]; break;
    }
    return v;
}

__device__ __forceinline__ float evalcol(int desc, const float* __restrict__ zn,
                                         const float* __restrict__ dv) {
    int kind = desc >> 24;
    if (kind >= 16) {
        int a = (desc >> 12) & 0xFFF;
        float dd = dv[a];
        float v;
        switch (kind - 16) {
            case 0: v = dd; break;
            case 1: v = frcp(dd + 1e-3f); break;
            case 2: v = frcp(dd * dd + 1e-3f); break;
            case 3: { float d2 = dd * dd; v = frcp(d2 * dd + 1e-3f); } break;
            case 4: { float d2 = dd * dd; v = frcp(d2 * d2 + 1e-3f); } break;
            case 5: { float d2 = dd * dd; v = frcp(d2 * d2 * dd + 1e-3f); } break;
            case 6: { float d2 = dd * dd; float d4 = d2 * d2; v = frcp(d4 * d2 + 1e-3f); } break;
            case 7: { float d2 = dd * dd; float d4 = d2 * d2; v = frcp(d4 * d4 + 1e-3f); } break;
            case 8: { float d2 = dd * dd; float d4 = d2 * d2; v = frcp(d4 * d4 * d2 + 1e-3f); } break;
            case 9: { float d2 = dd * dd; float d4 = d2 * d2; v = frcp(d4 * d4 * d4 + 1e-3f); } break;
            case 10:{ float d2 = dd * dd; float d4 = d2 * d2; float d8 = d4 * d4;
                      v = frcp(d8 * d4 * d2 + 1e-3f); } break;
            case 11: v = __expf(-dd); break;
            case 12: v = __expf(-dd) * frcp(dd + 1e-3f); break;
            default: v = __logf(dd + 1e-3f); break;
        }
        return fminf(fmaxf(v, -1e6f), 1e6f);
    }
    return evalrest(desc, zn);
}

// distance power chain: accumulate 14 values + squares for distance d
__device__ __forceinline__ void dchain(float d, float acc[28]) {
    float dpe = d + 1e-3f;
    float r1 = frcp(dpe);
    float d2 = d * d, d3 = d2 * d, d4 = d2 * d2, d6 = d3 * d3, d8 = d4 * d4;
    float v[14];
    v[0] = d;
    v[1] = r1;
    v[2] = frcp(d2 + 1e-3f);
    v[3] = frcp(d3 + 1e-3f);
    v[4] = frcp(d4 + 1e-3f);
    v[5] = frcp(d4 * d + 1e-3f);
    v[6] = frcp(d6 + 1e-3f);
    v[7] = frcp(d8 + 1e-3f);
    v[8] = frcp(d8 * d2 + 1e-3f);
    v[9] = frcp(d6 * d6 + 1e-3f);
    v[10] = frcp(d8 * d6 + 1e-3f);
    float e = __expf(-d);
    v[11] = e;
    v[12] = e * r1;
    v[13] = __logf(dpe);
    #pragma unroll
    for (int k = 0; k < 14; k++) {
        acc[k] += v[k];
        acc[14 + k] = fmaf(v[k], v[k], acc[14 + k]);
    }
}

__device__ __forceinline__ float pbc_dist(const float* zp, int bi, int bj) {
    float dx = zp[2 * bi]     - zp[2 * bj];
    float dy = zp[2 * bi + 1] - zp[2 * bj + 1];
    dx -= 10.0f * rintf(dx * 0.1f);
    dy -= 10.0f * rintf(dy * 0.1f);
    return fsqrt_a(dx * dx + dy * dy) + 1e-6f;
}

// ---------------- pass 1a: distance-derived columns ------------------------
__global__ void __launch_bounds__(512, 2)
p1dist_kernel(const float* __restrict__ z_flat) {
    __shared__ float s_zp[8][32];
    __shared__ float s_red[NDV];
    const int tid = threadIdx.x;
    const int r0 = tid >> 7, c0 = tid & 127;
    const int bp = tid % 120, br = tid / 120;
    int bi = 0, bj = 0;
    if (tid < 480) triu_pair(bp, 16, bi, bj);
    const bool zkeep = ((c0 & 7) < 2);
    const int zslot = ((c0 >> 3) << 1) | (c0 & 7);

    float acc[28];
    #pragma unroll
    for (int k = 0; k < 28; k++) acc[k] = 0.f;

    float za = z_flat[(blockIdx.x * 8 + r0) * 128 + c0];
    float zb = z_flat[(blockIdx.x * 8 + r0 + 4) * 128 + c0];
    for (int g = blockIdx.x; g < NG8; g += GRID_P) {
        if (zkeep) {
            s_zp[r0][zslot]     = fminf(fmaxf(za, -1e6f), 1e6f);
            s_zp[r0 + 4][zslot] = fminf(fmaxf(zb, -1e6f), 1e6f);
        }
        __syncthreads();
        int gn = g + GRID_P;
        float za_n = 0.f, zb_n = 0.f;
        if (gn < NG8) {
            za_n = z_flat[(gn * 8 + r0) * 128 + c0];
            zb_n = z_flat[(gn * 8 + r0 + 4) * 128 + c0];
        }
        if (tid < 480) {
            dchain(pbc_dist(s_zp[br], bi, bj), acc);
            dchain(pbc_dist(s_zp[br + 4], bi, bj), acc);
        }
        __syncthreads();
        za = za_n; zb = zb_n;
    }
    if (tid < 480 && br == 0) {
        #pragma unroll
        for (int k = 0; k < 28; k++) s_red[bp * 28 + k] = acc[k];
    }
    __syncthreads();
    for (int s = 1; s < 4; s++) {
        if (tid < 480 && br == s) {
            #pragma unroll
            for (int k = 0; k < 28; k++) s_red[bp * 28 + k] += acc[k];
        }
        __syncthreads();
    }
    for (int v = tid; v < NDV; v += 512)
        g_scr_d[blockIdx.x * NDV + v] = s_red[v];
}

// ---------------- pass 1b: non-distance columns ----------------------------
__global__ void __launch_bounds__(512, 2)
p1rest_kernel(const float* __restrict__ z_flat,
              const float* __restrict__ z_mean,
              const float* __restrict__ z_std) {
    __shared__ float s_zn[8][128];
    const int tid = threadIdx.x;
    const int r0 = tid >> 7, c0 = tid & 127;
    const float zma = z_mean[c0];
    const float zsia = frcp(z_std[c0]);

    int desc[5]; bool val[5];
    #pragma unroll
    for (int k = 0; k < 5; k++) {
        int i = tid + k * 512;
        val[k] = (i < NRV);
        int col = (i < 128) ? i : i + 1680;
        desc[k] = val[k] ? decode(col) : 0;
    }
    float fs[5], fq[5];
    #pragma unroll
    for (int k = 0; k < 5; k++) { fs[k] = 0.f; fq[k] = 0.f; }

    float za = z_flat[(blockIdx.x * 8 + r0) * 128 + c0];
    float zb = z_flat[(blockIdx.x * 8 + r0 + 4) * 128 + c0];
    for (int g = blockIdx.x; g < NG8; g += GRID_P) {
        s_zn[r0][c0]     = (fminf(fmaxf(za, -1e6f), 1e6f) - zma) * zsia;
        s_zn[r0 + 4][c0] = (fminf(fmaxf(zb, -1e6f), 1e6f) - zma) * zsia;
        __syncthreads();
        int gn = g + GRID_P;
        float za_n = 0.f, zb_n = 0.f;
        if (gn < NG8) {
            za_n = z_flat[(gn * 8 + r0) * 128 + c0];
            zb_n = z_flat[(gn * 8 + r0 + 4) * 128 + c0];
        }
        #pragma unroll
        for (int r = 0; r < 8; r++) {
            const float* zn = s_zn[r];
            #pragma unroll
            for (int k = 0; k < 5; k++) {
                if (val[k]) {
                    float v = evalrest(desc[k], zn);
                    fs[k] += v;
                    fq[k] = fmaf(v, v, fq[k]);
                }
            }
        }
        __syncthreads();
        za = za_n; zb = zb_n;
    }
    #pragma unroll
    for (int k = 0; k < 5; k++) {
        int i = tid + k * 512;
        if (val[k]) {
            g_scr_r[blockIdx.x * (2 * NRV) + i] = fs[k];
            g_scr_r[blockIdx.x * (2 * NRV) + NRV + i] = fq[k];
        }
    }
}

// ---------------- reduce stage 1: 296 partials -> 8 f64 chunks -------------
__global__ void __launch_bounds__(1024, 2)
reduce1_kernel() {
    int t = blockIdx.x * 1024 + threadIdx.x;
    int chunk = t / NVAL;
    int v = t - chunk * NVAL;
    if (chunk >= 8) return;
    double s = 0.0;
    int b0 = chunk * CHUNK;
    if (v < NDV) {
        #pragma unroll 4
        for (int b = b0; b < b0 + CHUNK; b++) s += (double)g_scr_d[b * NDV + v];
    } else {
        int i = v - NDV;
        #pragma unroll 4
        for (int b = b0; b < b0 + CHUNK; b++) s += (double)g_scr_r[b * (2 * NRV) + i];
    }
    g_part[chunk * NVAL + v] = s;
}

// ---------------- keys: fold 8 partials -> monotone u64 key (built ONCE) ---
__global__ void __launch_bounds__(256, 4)
keys_kernel() {
    int c = blockIdx.x * 256 + threadIdx.x;
    if (c >= 4096) return;
    unsigned long long key = 0ull;
    if (c < NCOLS) {
        int vs, vq;
        if (c < 128)        { vs = NDV + c; vq = NDV + NRV + c; }
        else if (c < 1808)  { int q = c - 128; int kk = q / 120; int pr = q % 120;
                              vs = pr * 28 + kk; vq = vs + 14; }
        else                { int i = c - 1680; vs = NDV + i; vq = NDV + NRV + i; }
        double s = 0.0, qq = 0.0;
        #pragma unroll
        for (int ch = 0; ch < 8; ch++) {
            s  += g_part[ch * NVAL + vs];
            qq += g_part[ch * NVAL + vq];
        }
        double var = (qq - s * (s * (1.0 / 32768.0))) * (1.0 / 32767.0);
        float fv = (float)var;
        unsigned u = __float_as_uint(fv);
        u = (u & 0x80000000u) ? ~u : (u | 0x80000000u);
        key = ((unsigned long long)u << 32) |
              (unsigned long long)(0xFFFFFFFFu - (unsigned)c);
    }
    g_key[c] = key;
}

// ---------------- rank-by-counting: exact top-1000 order -------------------
__global__ void __launch_bounds__(128, 8)
rank_kernel() {
    __shared__ unsigned long long sk[4096];
    const int tid = threadIdx.x;
    for (int i = tid; i < 4096; i += 128) sk[i] = g_key[i];
    __syncthreads();
    int c = blockIdx.x * 128 + tid;
    unsigned long long mykey = sk[c];
    int r = 0;
    #pragma unroll 8
    for (int i = 0; i < 4096; i++) r += (sk[i] > mykey);
    if (c < NCOLS && r < 1000) g_top[r] = c;
}

// ---------------- selection + class sort ------------------------------------
__global__ void __launch_bounds__(512, 1)
sel_kernel(const int* __restrict__ feature_mask) {
    __shared__ int s_selcol[512];
    __shared__ unsigned s_key[512];
    const int tid = threadIdx.x;
    int colid = g_top[feature_mask[tid]];
    s_selcol[tid] = colid;
    unsigned cls = (unsigned)(decode(colid) >> 24);
    s_key[tid] = (cls << 16) | (unsigned)tid;
    __syncthreads();
    for (int k = 2; k <= 512; k <<= 1) {
        for (int j = k >> 1; j > 0; j >>= 1) {
            int ixj = tid ^ j;
            if (ixj > tid) {
                unsigned a = s_key[tid], b = s_key[ixj];
                bool up = ((tid & k) == 0);
                if (up ? (a > b) : (a < b)) { s_key[tid] = b; s_key[ixj] = a; }
            }
            __syncthreads();
        }
    }
    unsigned key = s_key[tid];
    int j = (int)(key & 0xFFFFu);
    g_sel_j[tid] = j;
    g_sel_desc[tid] = decode(s_selcol[j]);
}

// ---------------- gather ----------------------------------------------------
__global__ void __launch_bounds__(512, 2)
gather_kernel(const float* __restrict__ z_flat,
              const float* __restrict__ z_mean,
              const float* __restrict__ z_std,
              const float* __restrict__ x_poly_mean,
              const float* __restrict__ x_poly_std,
              const int* __restrict__ feature_mask,
              float* __restrict__ out) {
    __shared__ float s_zn[8][128];
    __shared__ float s_zp[8][32];
    __shared__ float s_d[8][120];
    __shared__ float s_out[8][512];
    const int tid = threadIdx.x;
    const int desc = g_sel_desc[tid];
    const int j = g_sel_j[tid];
    const int m = feature_mask[j];
    const float mj = x_poly_mean[m];
    const float sji = frcp(x_poly_std[m]);

    const int r0 = tid >> 7, c0 = tid & 127;
    const float zma = z_mean[c0];
    const float zsia = frcp(z_std[c0]);
    const int bp = tid % 120, br = tid / 120;
    int bi = 0, bj = 0;
    if (tid < 480) triu_pair(bp, 16, bi, bj);
    const bool zkeep = ((c0 & 7) < 2);
    const int zslot = ((c0 >> 3) << 1) | (c0 & 7);

    float za = z_flat[(blockIdx.x * 8 + r0) * 128 + c0];
    float zb = z_flat[(blockIdx.x * 8 + r0 + 4) * 128 + c0];
    for (int g = blockIdx.x; g < NG8; g += GRID_P) {
        float zac = fminf(fmaxf(za, -1e6f), 1e6f);
        float zbc = fminf(fmaxf(zb, -1e6f), 1e6f);
        s_zn[r0][c0]     = (zac - zma) * zsia;
        s_zn[r0 + 4][c0] = (zbc - zma) * zsia;
        if (zkeep) { s_zp[r0][zslot] = zac; s_zp[r0 + 4][zslot] = zbc; }
        __syncthreads();
        int gn = g + GRID_P;
        float za_n = 0.f, zb_n = 0.f;
        if (gn < NG8) {
            za_n = z_flat[(gn * 8 + r0) * 128 + c0];
            zb_n = z_flat[(gn * 8 + r0 + 4) * 128 + c0];
        }
        if (tid < 480) {
            s_d[br][bp]     = pbc_dist(s_zp[br], bi, bj);
            s_d[br + 4][bp] = pbc_dist(s_zp[br + 4], bi, bj);
        }
        __syncthreads();
        #pragma unroll
        for (int r = 0; r < 8; r++) {
            float v = evalcol(desc, s_zn[r], s_d[r]);
            if (isnan(v)) v = 0.0f;
            else if (isinf(v)) v = (v > 0.0f) ? 1e9f : -1e9f;
            v = fminf(fmaxf(v, -1e12f), 1e12f);
            s_out[r][j] = (v - mj) * sji;
        }
        __syncthreads();
        #pragma unroll
        for (int w = 0; w < 2; w++) {
            int f = tid + w * 512;            // float4 index within 8x512 tile
            int r = f >> 7, c4 = f & 127;
            float4 wv = *(const float4*)&s_out[r][c4 * 4];
            *(float4*)&out[(size_t)(g * 8 + r) * 512 + c4 * 4] = wv;
        }
        za = za_n; zb = zb_n;
    }
}

extern "C" void kernel_launch(void* const* d_in, const int* in_sizes, int n_in,
                              void* d_out, int out_size) {
    const float* z_flat      = (const float*)d_in[0];
    const float* z_mean      = (const float*)d_in[1];
    const float* z_std       = (const float*)d_in[2];
    const float* x_poly_mean = (const float*)d_in[3];
    const float* x_poly_std  = (const float*)d_in[4];
    const int*   feature_mask = (const int*)d_in[5];
    float* out = (float*)d_out;

    p1dist_kernel<<<GRID_P, 512>>>(z_flat);
    p1rest_kernel<<<GRID_P, 512>>>(z_flat, z_mean, z_std);
    reduce1_kernel<<<(8 * NVAL + 1023) / 1024, 1024>>>();
    keys_kernel<<<16, 256>>>();
    rank_kernel<<<32, 128>>>();
    sel_kernel<<<1, 512>>>(feature_mask);
    gather_kernel<<<GRID_P, 512>>>(z_flat, z_mean, z_std,
                                   x_poly_mean, x_poly_std, feature_mask, out);
}

// round 7
// speedup vs baseline: 4.3473x; 1.0021x over previous
#include <cuda_runtime.h>
#include <math.h>

#define NCOLS 3872
#define NROWS 32768
#define NG8   (NROWS / 8)
#define GRID_P 296
#define NDV 3360            // 120 pairs * 28 (14 sum + 14 sumsq)
#define NRV 2192            // non-dist columns
#define NVAL (NDV + 2 * NRV)   // 7744
#define CHUNK 37               // 296 / 8

__device__ float  g_scr_d[GRID_P * NDV];
__device__ float  g_scr_r[GRID_P * NRV * 2];
__device__ double g_part[8 * NVAL];
__device__ unsigned long long g_key[4096];
__device__ int    g_top[1000];
__device__ int    g_sel_desc[512];
__device__ int    g_sel_j[512];

__device__ __forceinline__ float frcp(float x) {
    float r; asm("rcp.approx.f32 %0, %1;" : "=f"(r) : "f"(x)); return r;
}
__device__ __forceinline__ float fsqrt_a(float x) {
    float r; asm("sqrt.approx.f32 %0, %1;" : "=f"(r) : "f"(x)); return r;
}

__device__ __forceinline__ void triu_pair(int p, int n, int &i, int &j) {
    int ii = 0, rem = p, cnt = n - 1;
    while (rem >= cnt) { rem -= cnt; cnt--; ii++; }
    i = ii; j = ii + 1 + rem;
}

// Column descriptor: kind<<24 | a<<12 | b
__device__ __forceinline__ int decode(int c) {
    int kind, a, b = 0;
    if (c < 128)       { kind = 0; a = c; }
    else if (c < 1808) { int q = c - 128; kind = 16 + q / 120; a = q % 120; }
    else if (c < 1936) { kind = 1; a = c - 1808; }
    else if (c < 2064) { kind = 2; a = c - 1936; }
    else if (c < 2192) { kind = 3; a = c - 2064; }
    else if (c < 2320) { kind = 4; a = c - 2192; }
    else if (c < 2448) { kind = 5; a = c - 2320; }
    else if (c < 2464) { kind = 6; a = (c - 2448) * 8; }
    else if (c < 2912) {
        int idx = c - 2464; int n = idx / 28, pr = idx % 28;
        int i, j; triu_pair(pr, 8, i, j);
        kind = 7; a = n * 8 + i; b = n * 8 + j;
    } else {
        int idx = c - 2912; int pr = idx / 8, k = idx % 8;
        int i, j; triu_pair(pr, 16, i, j);
        kind = 7; a = i * 8 + k; b = j * 8 + k;
    }
    return (kind << 24) | (a << 12) | b;
}

__device__ __forceinline__ float evalrest(int desc, const float* __restrict__ zn) {
    int kind = desc >> 24;
    int a = (desc >> 12) & 0xFFF;
    int b = desc & 0xFFF;
    float v;
    switch (kind) {
        case 0: v = zn[a]; break;
        case 1: { float t = zn[a]; v = t * t; } break;
        case 2: v = __sinf(zn[a]); break;
        case 3: v = __cosf(zn[a]); break;
        case 4: v = __logf(fabsf(zn[a]) + 1e-3f); break;
        case 5: v = __expf(fminf(fmaxf(zn[a], -10.0f), 2.0f)); break;
        case 6: { float s = 0.0f;
                  #pragma unroll
                  for (int k = 4; k < 8; k++) { float t = zn[a + k]; s += t * t; }
                  v = s; } break;
        default: v = zn[a] * zn[b]; break;
    }
    return v;
}

__device__ __forceinline__ float evalcol(int desc, const float* __restrict__ zn,
                                         const float* __restrict__ dv) {
    int kind = desc >> 24;
    if (kind >= 16) {
        int a = (desc >> 12) & 0xFFF;
        float dd = dv[a];
        float v;
        switch (kind - 16) {
            case 0: v = dd; break;
            case 1: v = frcp(dd + 1e-3f); break;
            case 2: v = frcp(dd * dd + 1e-3f); break;
            case 3: { float d2 = dd * dd; v = frcp(d2 * dd + 1e-3f); } break;
            case 4: { float d2 = dd * dd; v = frcp(d2 * d2 + 1e-3f); } break;
            case 5: { float d2 = dd * dd; v = frcp(d2 * d2 * dd + 1e-3f); } break;
            case 6: { float d2 = dd * dd; float d4 = d2 * d2; v = frcp(d4 * d2 + 1e-3f); } break;
            case 7: { float d2 = dd * dd; float d4 = d2 * d2; v = frcp(d4 * d4 + 1e-3f); } break;
            case 8: { float d2 = dd * dd; float d4 = d2 * d2; v = frcp(d4 * d4 * d2 + 1e-3f); } break;
            case 9: { float d2 = dd * dd; float d4 = d2 * d2; v = frcp(d4 * d4 * d4 + 1e-3f); } break;
            case 10:{ float d2 = dd * dd; float d4 = d2 * d2; float d8 = d4 * d4;
                      v = frcp(d8 * d4 * d2 + 1e-3f); } break;
            case 11: v = __expf(-dd); break;
            case 12: v = __expf(-dd) * frcp(dd + 1e-3f); break;
            default: v = __logf(dd + 1e-3f); break;
        }
        return fminf(fmaxf(v, -1e6f), 1e6f);
    }
    return evalrest(desc, zn);
}

// distance power chain: accumulate 14 values + squares for distance d
__device__ __forceinline__ void dchain(float d, float acc[28]) {
    float dpe = d + 1e-3f;
    float r1 = frcp(dpe);
    float d2 = d * d, d3 = d2 * d, d4 = d2 * d2, d6 = d3 * d3, d8 = d4 * d4;
    float v[14];
    v[0] = d;
    v[1] = r1;
    v[2] = frcp(d2 + 1e-3f);
    v[3] = frcp(d3 + 1e-3f);
    v[4] = frcp(d4 + 1e-3f);
    v[5] = frcp(d4 * d + 1e-3f);
    v[6] = frcp(d6 + 1e-3f);
    v[7] = frcp(d8 + 1e-3f);
    v[8] = frcp(d8 * d2 + 1e-3f);
    v[9] = frcp(d6 * d6 + 1e-3f);
    v[10] = frcp(d8 * d6 + 1e-3f);
    float e = __expf(-d);
    v[11] = e;
    v[12] = e * r1;
    v[13] = __logf(dpe);
    #pragma unroll
    for (int k = 0; k < 14; k++) {
        acc[k] += v[k];
        acc[14 + k] = fmaf(v[k], v[k], acc[14 + k]);
    }
}

__device__ __forceinline__ float pbc_dist(const float* zp, int bi, int bj) {
    float dx = zp[2 * bi]     - zp[2 * bj];
    float dy = zp[2 * bi + 1] - zp[2 * bj + 1];
    dx -= 10.0f * rintf(dx * 0.1f);
    dy -= 10.0f * rintf(dy * 0.1f);
    return fsqrt_a(dx * dx + dy * dy) + 1e-6f;
}

// ---------------- pass 1 (fused, block-specialized) -------------------------
// blocks [0, GRID_P)        : distance-derived columns (MUFU-heavy)
// blocks [GRID_P, 2*GRID_P) : non-distance columns (FMA/LDS-heavy)
// 2 CTAs/SM co-schedule one of each -> complementary pipe usage.
__global__ void __launch_bounds__(512, 2)
pass1_kernel(const float* __restrict__ z_flat,
             const float* __restrict__ z_mean,
             const float* __restrict__ z_std) {
    const int tid = threadIdx.x;
    const int r0 = tid >> 7, c0 = tid & 127;

    if (blockIdx.x < GRID_P) {
        // ================= distance body =================
        __shared__ float s_zp[8][32];
        __shared__ float s_red[NDV];
        const int bid = blockIdx.x;
        const int bp = tid % 120, br = tid / 120;
        int bi = 0, bj = 0;
        if (tid < 480) triu_pair(bp, 16, bi, bj);
        const bool zkeep = ((c0 & 7) < 2);
        const int zslot = ((c0 >> 3) << 1) | (c0 & 7);

        float acc[28];
        #pragma unroll
        for (int k = 0; k < 28; k++) acc[k] = 0.f;

        float za = z_flat[(bid * 8 + r0) * 128 + c0];
        float zb = z_flat[(bid * 8 + r0 + 4) * 128 + c0];
        for (int g = bid; g < NG8; g += GRID_P) {
            if (zkeep) {
                s_zp[r0][zslot]     = fminf(fmaxf(za, -1e6f), 1e6f);
                s_zp[r0 + 4][zslot] = fminf(fmaxf(zb, -1e6f), 1e6f);
            }
            __syncthreads();
            int gn = g + GRID_P;
            float za_n = 0.f, zb_n = 0.f;
            if (gn < NG8) {
                za_n = z_flat[(gn * 8 + r0) * 128 + c0];
                zb_n = z_flat[(gn * 8 + r0 + 4) * 128 + c0];
            }
            if (tid < 480) {
                dchain(pbc_dist(s_zp[br], bi, bj), acc);
                dchain(pbc_dist(s_zp[br + 4], bi, bj), acc);
            }
            __syncthreads();
            za = za_n; zb = zb_n;
        }
        if (tid < 480 && br == 0) {
            #pragma unroll
            for (int k = 0; k < 28; k++) s_red[bp * 28 + k] = acc[k];
        }
        __syncthreads();
        for (int s = 1; s < 4; s++) {
            if (tid < 480 && br == s) {
                #pragma unroll
                for (int k = 0; k < 28; k++) s_red[bp * 28 + k] += acc[k];
            }
            __syncthreads();
        }
        for (int v = tid; v < NDV; v += 512)
            g_scr_d[bid * NDV + v] = s_red[v];
    } else {
        // ================= rest body =================
        __shared__ float s_zn[8][128];
        const int bid = blockIdx.x - GRID_P;
        const float zma = z_mean[c0];
        const float zsia = frcp(z_std[c0]);

        int desc[5]; bool val[5];
        #pragma unroll
        for (int k = 0; k < 5; k++) {
            int i = tid + k * 512;
            val[k] = (i < NRV);
            int col = (i < 128) ? i : i + 1680;
            desc[k] = val[k] ? decode(col) : 0;
        }
        float fs[5], fq[5];
        #pragma unroll
        for (int k = 0; k < 5; k++) { fs[k] = 0.f; fq[k] = 0.f; }

        float za = z_flat[(bid * 8 + r0) * 128 + c0];
        float zb = z_flat[(bid * 8 + r0 + 4) * 128 + c0];
        for (int g = bid; g < NG8; g += GRID_P) {
            s_zn[r0][c0]     = (fminf(fmaxf(za, -1e6f), 1e6f) - zma) * zsia;
            s_zn[r0 + 4][c0] = (fminf(fmaxf(zb, -1e6f), 1e6f) - zma) * zsia;
            __syncthreads();
            int gn = g + GRID_P;
            float za_n = 0.f, zb_n = 0.f;
            if (gn < NG8) {
                za_n = z_flat[(gn * 8 + r0) * 128 + c0];
                zb_n = z_flat[(gn * 8 + r0 + 4) * 128 + c0];
            }
            #pragma unroll
            for (int r = 0; r < 8; r++) {
                const float* zn = s_zn[r];
                #pragma unroll
                for (int k = 0; k < 5; k++) {
                    if (val[k]) {
                        float v = evalrest(desc[k], zn);
                        fs[k] += v;
                        fq[k] = fmaf(v, v, fq[k]);
                    }
                }
            }
            __syncthreads();
            za = za_n; zb = zb_n;
        }
        #pragma unroll
        for (int k = 0; k < 5; k++) {
            int i = tid + k * 512;
            if (val[k]) {
                g_scr_r[bid * (2 * NRV) + i] = fs[k];
                g_scr_r[bid * (2 * NRV) + NRV + i] = fq[k];
            }
        }
    }
}

// ---------------- reduce stage 1: 296 partials -> 8 f64 chunks -------------
__global__ void __launch_bounds__(1024, 2)
reduce1_kernel() {
    int t = blockIdx.x * 1024 + threadIdx.x;
    int chunk = t / NVAL;
    int v = t - chunk * NVAL;
    if (chunk >= 8) return;
    double s = 0.0;
    int b0 = chunk * CHUNK;
    if (v < NDV) {
        #pragma unroll 4
        for (int b = b0; b < b0 + CHUNK; b++) s += (double)g_scr_d[b * NDV + v];
    } else {
        int i = v - NDV;
        #pragma unroll 4
        for (int b = b0; b < b0 + CHUNK; b++) s += (double)g_scr_r[b * (2 * NRV) + i];
    }
    g_part[chunk * NVAL + v] = s;
}

// ---------------- keys: fold 8 partials -> monotone u64 key (built ONCE) ---
__global__ void __launch_bounds__(256, 4)
keys_kernel() {
    int c = blockIdx.x * 256 + threadIdx.x;
    if (c >= 4096) return;
    unsigned long long key = 0ull;
    if (c < NCOLS) {
        int vs, vq;
        if (c < 128)        { vs = NDV + c; vq = NDV + NRV + c; }
        else if (c < 1808)  { int q = c - 128; int kk = q / 120; int pr = q % 120;
                              vs = pr * 28 + kk; vq = vs + 14; }
        else                { int i = c - 1680; vs = NDV + i; vq = NDV + NRV + i; }
        double s = 0.0, qq = 0.0;
        #pragma unroll
        for (int ch = 0; ch < 8; ch++) {
            s  += g_part[ch * NVAL + vs];
            qq += g_part[ch * NVAL + vq];
        }
        double var = (qq - s * (s * (1.0 / 32768.0))) * (1.0 / 32767.0);
        float fv = (float)var;
        unsigned u = __float_as_uint(fv);
        u = (u & 0x80000000u) ? ~u : (u | 0x80000000u);
        key = ((unsigned long long)u << 32) |
              (unsigned long long)(0xFFFFFFFFu - (unsigned)c);
    }
    g_key[c] = key;
}

// ---------------- rank-by-counting: exact top-1000 order -------------------
__global__ void __launch_bounds__(128, 8)
rank_kernel() {
    __shared__ unsigned long long sk[4096];
    const int tid = threadIdx.x;
    for (int i = tid; i < 4096; i += 128) sk[i] = g_key[i];
    __syncthreads();
    int c = blockIdx.x * 128 + tid;
    unsigned long long mykey = sk[c];
    int r = 0;
    #pragma unroll 8
    for (int i = 0; i < 4096; i++) r += (sk[i] > mykey);
    if (c < NCOLS && r < 1000) g_top[r] = c;
}

// ---------------- selection + class sort ------------------------------------
__global__ void __launch_bounds__(512, 1)
sel_kernel(const int* __restrict__ feature_mask) {
    __shared__ int s_selcol[512];
    __shared__ unsigned s_key[512];
    const int tid = threadIdx.x;
    int colid = g_top[feature_mask[tid]];
    s_selcol[tid] = colid;
    unsigned cls = (unsigned)(decode(colid) >> 24);
    s_key[tid] = (cls << 16) | (unsigned)tid;
    __syncthreads();
    for (int k = 2; k <= 512; k <<= 1) {
        for (int j = k >> 1; j > 0; j >>= 1) {
            int ixj = tid ^ j;
            if (ixj > tid) {
                unsigned a = s_key[tid], b = s_key[ixj];
                bool up = ((tid & k) == 0);
                if (up ? (a > b) : (a < b)) { s_key[tid] = b; s_key[ixj] = a; }
            }
            __syncthreads();
        }
    }
    unsigned key = s_key[tid];
    int j = (int)(key & 0xFFFFu);
    g_sel_j[tid] = j;
    g_sel_desc[tid] = decode(s_selcol[j]);
}

// ---------------- gather ----------------------------------------------------
__global__ void __launch_bounds__(512, 2)
gather_kernel(const float* __restrict__ z_flat,
              const float* __restrict__ z_mean,
              const float* __restrict__ z_std,
              const float* __restrict__ x_poly_mean,
              const float* __restrict__ x_poly_std,
              const int* __restrict__ feature_mask,
              float* __restrict__ out) {
    __shared__ float s_zn[8][128];
    __shared__ float s_zp[8][32];
    __shared__ float s_d[8][120];
    __shared__ float s_out[8][512];
    const int tid = threadIdx.x;
    const int desc = g_sel_desc[tid];
    const int j = g_sel_j[tid];
    const int m = feature_mask[j];
    const float mj = x_poly_mean[m];
    const float sji = frcp(x_poly_std[m]);

    const int r0 = tid >> 7, c0 = tid & 127;
    const float zma = z_mean[c0];
    const float zsia = frcp(z_std[c0]);
    const int bp = tid % 120, br = tid / 120;
    int bi = 0, bj = 0;
    if (tid < 480) triu_pair(bp, 16, bi, bj);
    const bool zkeep = ((c0 & 7) < 2);
    const int zslot = ((c0 >> 3) << 1) | (c0 & 7);

    float za = z_flat[(blockIdx.x * 8 + r0) * 128 + c0];
    float zb = z_flat[(blockIdx.x * 8 + r0 + 4) * 128 + c0];
    for (int g = blockIdx.x; g < NG8; g += GRID_P) {
        float zac = fminf(fmaxf(za, -1e6f), 1e6f);
        float zbc = fminf(fmaxf(zb, -1e6f), 1e6f);
        s_zn[r0][c0]     = (zac - zma) * zsia;
        s_zn[r0 + 4][c0] = (zbc - zma) * zsia;
        if (zkeep) { s_zp[r0][zslot] = zac; s_zp[r0 + 4][zslot] = zbc; }
        __syncthreads();
        int gn = g + GRID_P;
        float za_n = 0.f, zb_n = 0.f;
        if (gn < NG8) {
            za_n = z_flat[(gn * 8 + r0) * 128 + c0];
            zb_n = z_flat[(gn * 8 + r0 + 4) * 128 + c0];
        }
        if (tid < 480) {
            s_d[br][bp]     = pbc_dist(s_zp[br], bi, bj);
            s_d[br + 4][bp] = pbc_dist(s_zp[br + 4], bi, bj);
        }
        __syncthreads();
        #pragma unroll
        for (int r = 0; r < 8; r++) {
            float v = evalcol(desc, s_zn[r], s_d[r]);
            if (isnan(v)) v = 0.0f;
            else if (isinf(v)) v = (v > 0.0f) ? 1e9f : -1e9f;
            v = fminf(fmaxf(v, -1e12f), 1e12f);
            s_out[r][j] = (v - mj) * sji;
        }
        __syncthreads();
        #pragma unroll
        for (int w = 0; w < 2; w++) {
            int f = tid + w * 512;            // float4 index within 8x512 tile
            int r = f >> 7, c4 = f & 127;
            float4 wv = *(const float4*)&s_out[r][c4 * 4];
            *(float4*)&out[(size_t)(g * 8 + r) * 512 + c4 * 4] = wv;
        }
        za = za_n; zb = zb_n;
    }
}

extern "C" void kernel_launch(void* const* d_in, const int* in_sizes, int n_in,
                              void* d_out, int out_size) {
    const float* z_flat      = (const float*)d_in[0];
    const float* z_mean      = (const float*)d_in[1];
    const float* z_std       = (const float*)d_in[2];
    const float* x_poly_mean = (const float*)d_in[3];
    const float* x_poly_std  = (const float*)d_in[4];
    const int*   feature_mask = (const int*)d_in[5];
    float* out = (float*)d_out;

    pass1_kernel<<<2 * GRID_P, 512>>>(z_flat, z_mean, z_std);
    reduce1_kernel<<<(8 * NVAL + 1023) / 1024, 1024>>>();
    keys_kernel<<<16, 256>>>();
    rank_kernel<<<32, 128>>>();
    sel_kernel<<<1, 512>>>(feature_mask);
    gather_kernel<<<GRID_P, 512>>>(z_flat, z_mean, z_std,
                                   x_poly_mean, x_poly_std, feature_mask, out);
}

// round 8
// speedup vs baseline: 4.4384x; 1.0210x over previous
#include <cuda_runtime.h>
#include <math.h>

#define NCOLS 3872
#define NROWS 32768
#define NG8   (NROWS / 8)
#define GRID_P 296
#define NDV 3360            // 120 pairs * 28 (14 sum + 14 sumsq)
#define NRV 2192            // non-dist columns
#define NVAL (NDV + 2 * NRV)   // 7744
#define CHUNK 37               // 296 / 8

__device__ float  g_scr_d[GRID_P * NDV];
__device__ float  g_scr_r[GRID_P * NRV * 2];
__device__ double g_part[8 * NVAL];
__device__ unsigned long long g_key[4096];
__device__ int    g_rank[4096];
__device__ int    g_top[1000];
__device__ int    g_sel_desc[512];
__device__ int    g_sel_j[512];

__device__ __forceinline__ float frcp(float x) {
    float r; asm("rcp.approx.f32 %0, %1;" : "=f"(r) : "f"(x)); return r;
}
__device__ __forceinline__ float fsqrt_a(float x) {
    float r; asm("sqrt.approx.f32 %0, %1;" : "=f"(r) : "f"(x)); return r;
}

__device__ __forceinline__ void triu_pair(int p, int n, int &i, int &j) {
    int ii = 0, rem = p, cnt = n - 1;
    while (rem >= cnt) { rem -= cnt; cnt--; ii++; }
    i = ii; j = ii + 1 + rem;
}

// Column descriptor: kind<<24 | a<<12 | b
__device__ __forceinline__ int decode(int c) {
    int kind, a, b = 0;
    if (c < 128)       { kind = 0; a = c; }
    else if (c < 1808) { int q = c - 128; kind = 16 + q / 120; a = q % 120; }
    else if (c < 1936) { kind = 1; a = c - 1808; }
    else if (c < 2064) { kind = 2; a = c - 1936; }
    else if (c < 2192) { kind = 3; a = c - 2064; }
    else if (c < 2320) { kind = 4; a = c - 2192; }
    else if (c < 2448) { kind = 5; a = c - 2320; }
    else if (c < 2464) { kind = 6; a = (c - 2448) * 8; }
    else if (c < 2912) {
        int idx = c - 2464; int n = idx / 28, pr = idx % 28;
        int i, j; triu_pair(pr, 8, i, j);
        kind = 7; a = n * 8 + i; b = n * 8 + j;
    } else {
        int idx = c - 2912; int pr = idx / 8, k = idx % 8;
        int i, j; triu_pair(pr, 16, i, j);
        kind = 7; a = i * 8 + k; b = j * 8 + k;
    }
    return (kind << 24) | (a << 12) | b;
}

__device__ __forceinline__ float evalrest(int desc, const float* __restrict__ zn) {
    int kind = desc >> 24;
    int a = (desc >> 12) & 0xFFF;
    int b = desc & 0xFFF;
    float v;
    switch (kind) {
        case 0: v = zn[a]; break;
        case 1: { float t = zn[a]; v = t * t; } break;
        case 2: v = __sinf(zn[a]); break;
        case 3: v = __cosf(zn[a]); break;
        case 4: v = __logf(fabsf(zn[a]) + 1e-3f); break;
        case 5: v = __expf(fminf(fmaxf(zn[a], -10.0f), 2.0f)); break;
        case 6: { float s = 0.0f;
                  #pragma unroll
                  for (int k = 4; k < 8; k++) { float t = zn[a + k]; s += t * t; }
                  v = s; } break;
        default: v = zn[a] * zn[b]; break;
    }
    return v;
}

__device__ __forceinline__ float evalcol(int desc, const float* __restrict__ zn,
                                         const float* __restrict__ dv) {
    int kind = desc >> 24;
    if (kind >= 16) {
        int a = (desc >> 12) & 0xFFF;
        float dd = dv[a];
        float v;
        switch (kind - 16) {
            case 0: v = dd; break;
            case 1: v = frcp(dd + 1e-3f); break;
            case 2: v = frcp(dd * dd + 1e-3f); break;
            case 3: { float d2 = dd * dd; v = frcp(d2 * dd + 1e-3f); } break;
            case 4: { float d2 = dd * dd; v = frcp(d2 * d2 + 1e-3f); } break;
            case 5: { float d2 = dd * dd; v = frcp(d2 * d2 * dd + 1e-3f); } break;
            case 6: { float d2 = dd * dd; float d4 = d2 * d2; v = frcp(d4 * d2 + 1e-3f); } break;
            case 7: { float d2 = dd * dd; float d4 = d2 * d2; v = frcp(d4 * d4 + 1e-3f); } break;
            case 8: { float d2 = dd * dd; float d4 = d2 * d2; v = frcp(d4 * d4 * d2 + 1e-3f); } break;
            case 9: { float d2 = dd * dd; float d4 = d2 * d2; v = frcp(d4 * d4 * d4 + 1e-3f); } break;
            case 10:{ float d2 = dd * dd; float d4 = d2 * d2; float d8 = d4 * d4;
                      v = frcp(d8 * d4 * d2 + 1e-3f); } break;
            case 11: v = __expf(-dd); break;
            case 12: v = __expf(-dd) * frcp(dd + 1e-3f); break;
            default: v = __logf(dd + 1e-3f); break;
        }
        return fminf(fmaxf(v, -1e6f), 1e6f);
    }
    return evalrest(desc, zn);
}

// distance power chain: accumulate 14 values + squares for distance d
__device__ __forceinline__ void dchain(float d, float acc[28]) {
    float dpe = d + 1e-3f;
    float r1 = frcp(dpe);
    float d2 = d * d, d3 = d2 * d, d4 = d2 * d2, d6 = d3 * d3, d8 = d4 * d4;
    float v[14];
    v[0] = d;
    v[1] = r1;
    v[2] = frcp(d2 + 1e-3f);
    v[3] = frcp(d3 + 1e-3f);
    v[4] = frcp(d4 + 1e-3f);
    v[5] = frcp(d4 * d + 1e-3f);
    v[6] = frcp(d6 + 1e-3f);
    v[7] = frcp(d8 + 1e-3f);
    v[8] = frcp(d8 * d2 + 1e-3f);
    v[9] = frcp(d6 * d6 + 1e-3f);
    v[10] = frcp(d8 * d6 + 1e-3f);
    float e = __expf(-d);
    v[11] = e;
    v[12] = e * r1;
    v[13] = __logf(dpe);
    #pragma unroll
    for (int k = 0; k < 14; k++) {
        acc[k] += v[k];
        acc[14 + k] = fmaf(v[k], v[k], acc[14 + k]);
    }
}

__device__ __forceinline__ float pbc_dist(const float* zp, int bi, int bj) {
    float dx = zp[2 * bi]     - zp[2 * bj];
    float dy = zp[2 * bi + 1] - zp[2 * bj + 1];
    dx -= 10.0f * rintf(dx * 0.1f);
    dy -= 10.0f * rintf(dy * 0.1f);
    return fsqrt_a(dx * dx + dy * dy) + 1e-6f;
}

// ---------------- pass 1 (fused, role INTERLEAVED) --------------------------
// even blocks: distance body (MUFU-heavy); odd blocks: rest body (FMA-heavy).
// Adjacent blocks land in the same wave -> each SM hosts one of each.
__global__ void __launch_bounds__(512, 2)
pass1_kernel(const float* __restrict__ z_flat,
             const float* __restrict__ z_mean,
             const float* __restrict__ z_std) {
    const int tid = threadIdx.x;
    const int r0 = tid >> 7, c0 = tid & 127;
    const int bid = blockIdx.x >> 1;

    if ((blockIdx.x & 1) == 0) {
        // ================= distance body =================
        __shared__ float s_zp[8][32];
        __shared__ float s_red[NDV];
        const int bp = tid % 120, br = tid / 120;
        int bi = 0, bj = 0;
        if (tid < 480) triu_pair(bp, 16, bi, bj);
        const bool zkeep = ((c0 & 7) < 2);
        const int zslot = ((c0 >> 3) << 1) | (c0 & 7);

        float acc[28];
        #pragma unroll
        for (int k = 0; k < 28; k++) acc[k] = 0.f;

        float za = z_flat[(bid * 8 + r0) * 128 + c0];
        float zb = z_flat[(bid * 8 + r0 + 4) * 128 + c0];
        for (int g = bid; g < NG8; g += GRID_P) {
            if (zkeep) {
                s_zp[r0][zslot]     = fminf(fmaxf(za, -1e6f), 1e6f);
                s_zp[r0 + 4][zslot] = fminf(fmaxf(zb, -1e6f), 1e6f);
            }
            __syncthreads();
            int gn = g + GRID_P;
            float za_n = 0.f, zb_n = 0.f;
            if (gn < NG8) {
                za_n = z_flat[(gn * 8 + r0) * 128 + c0];
                zb_n = z_flat[(gn * 8 + r0 + 4) * 128 + c0];
            }
            if (tid < 480) {
                dchain(pbc_dist(s_zp[br], bi, bj), acc);
                dchain(pbc_dist(s_zp[br + 4], bi, bj), acc);
            }
            __syncthreads();
            za = za_n; zb = zb_n;
        }
        if (tid < 480 && br == 0) {
            #pragma unroll
            for (int k = 0; k < 28; k++) s_red[bp * 28 + k] = acc[k];
        }
        __syncthreads();
        for (int s = 1; s < 4; s++) {
            if (tid < 480 && br == s) {
                #pragma unroll
                for (int k = 0; k < 28; k++) s_red[bp * 28 + k] += acc[k];
            }
            __syncthreads();
        }
        for (int v = tid; v < NDV; v += 512)
            g_scr_d[bid * NDV + v] = s_red[v];
    } else {
        // ================= rest body =================
        __shared__ float s_zn[8][128];
        const float zma = z_mean[c0];
        const float zsia = frcp(z_std[c0]);

        int desc[5]; bool val[5];
        #pragma unroll
        for (int k = 0; k < 5; k++) {
            int i = tid + k * 512;
            val[k] = (i < NRV);
            int col = (i < 128) ? i : i + 1680;
            desc[k] = val[k] ? decode(col) : 0;
        }
        float fs[5], fq[5];
        #pragma unroll
        for (int k = 0; k < 5; k++) { fs[k] = 0.f; fq[k] = 0.f; }

        float za = z_flat[(bid * 8 + r0) * 128 + c0];
        float zb = z_flat[(bid * 8 + r0 + 4) * 128 + c0];
        for (int g = bid; g < NG8; g += GRID_P) {
            s_zn[r0][c0]     = (fminf(fmaxf(za, -1e6f), 1e6f) - zma) * zsia;
            s_zn[r0 + 4][c0] = (fminf(fmaxf(zb, -1e6f), 1e6f) - zma) * zsia;
            __syncthreads();
            int gn = g + GRID_P;
            float za_n = 0.f, zb_n = 0.f;
            if (gn < NG8) {
                za_n = z_flat[(gn * 8 + r0) * 128 + c0];
                zb_n = z_flat[(gn * 8 + r0 + 4) * 128 + c0];
            }
            #pragma unroll
            for (int r = 0; r < 8; r++) {
                const float* zn = s_zn[r];
                #pragma unroll
                for (int k = 0; k < 5; k++) {
                    if (val[k]) {
                        float v = evalrest(desc[k], zn);
                        fs[k] += v;
                        fq[k] = fmaf(v, v, fq[k]);
                    }
                }
            }
            __syncthreads();
            za = za_n; zb = zb_n;
        }
        #pragma unroll
        for (int k = 0; k < 5; k++) {
            int i = tid + k * 512;
            if (val[k]) {
                g_scr_r[bid * (2 * NRV) + i] = fs[k];
                g_scr_r[bid * (2 * NRV) + NRV + i] = fq[k];
            }
        }
    }
}

// ---------------- reduce stage 1: 296 partials -> 8 f64 chunks -------------
__global__ void __launch_bounds__(1024, 2)
reduce1_kernel() {
    int t = blockIdx.x * 1024 + threadIdx.x;
    int chunk = t / NVAL;
    int v = t - chunk * NVAL;
    if (chunk >= 8) return;
    double s = 0.0;
    int b0 = chunk * CHUNK;
    if (v < NDV) {
        #pragma unroll 4
        for (int b = b0; b < b0 + CHUNK; b++) s += (double)g_scr_d[b * NDV + v];
    } else {
        int i = v - NDV;
        #pragma unroll 4
        for (int b = b0; b < b0 + CHUNK; b++) s += (double)g_scr_r[b * (2 * NRV) + i];
    }
    g_part[chunk * NVAL + v] = s;
}

// ---------------- keys: fold 8 partials -> monotone u64 key; zero ranks ----
__global__ void __launch_bounds__(256, 4)
keys_kernel() {
    int c = blockIdx.x * 256 + threadIdx.x;
    if (c >= 4096) return;
    g_rank[c] = 0;
    unsigned long long key = 0ull;
    if (c < NCOLS) {
        int vs, vq;
        if (c < 128)        { vs = NDV + c; vq = NDV + NRV + c; }
        else if (c < 1808)  { int q = c - 128; int kk = q / 120; int pr = q % 120;
                              vs = pr * 28 + kk; vq = vs + 14; }
        else                { int i = c - 1680; vs = NDV + i; vq = NDV + NRV + i; }
        double s = 0.0, qq = 0.0;
        #pragma unroll
        for (int ch = 0; ch < 8; ch++) {
            s  += g_part[ch * NVAL + vs];
            qq += g_part[ch * NVAL + vq];
        }
        double var = (qq - s * (s * (1.0 / 32768.0))) * (1.0 / 32767.0);
        float fv = (float)var;
        unsigned u = __float_as_uint(fv);
        u = (u & 0x80000000u) ? ~u : (u | 0x80000000u);
        key = ((unsigned long long)u << 32) |
              (unsigned long long)(0xFFFFFFFFu - (unsigned)c);
    }
    g_key[c] = key;
}

// ---------------- rank: 2-D tiled counting (32 cand-groups x 4 slices) -----
__global__ void __launch_bounds__(128, 8)
rank_kernel() {
    __shared__ unsigned long long sk[1024];
    const int tid = threadIdx.x;
    const int cg = blockIdx.x & 31;       // candidate group
    const int sl = blockIdx.x >> 5;       // key slice
    for (int i = tid; i < 1024; i += 128) sk[i] = g_key[sl * 1024 + i];
    __syncthreads();
    int c = cg * 128 + tid;
    unsigned long long mykey = g_key[c];
    int r = 0;
    #pragma unroll 8
    for (int i = 0; i < 1024; i++) r += (sk[i] > mykey);
    if (r > 0) atomicAdd(&g_rank[c], r);
}

// ---------------- scatter: rank -> top table --------------------------------
__global__ void __launch_bounds__(256, 4)
scatter_kernel() {
    int c = blockIdx.x * 256 + threadIdx.x;
    if (c < NCOLS) {
        int r = g_rank[c];
        if (r < 1000) g_top[r] = c;
    }
}

// ---------------- selection + class sort ------------------------------------
__global__ void __launch_bounds__(512, 1)
sel_kernel(const int* __restrict__ feature_mask) {
    __shared__ int s_selcol[512];
    __shared__ unsigned s_key[512];
    const int tid = threadIdx.x;
    int colid = g_top[feature_mask[tid]];
    s_selcol[tid] = colid;
    unsigned cls = (unsigned)(decode(colid) >> 24);
    s_key[tid] = (cls << 16) | (unsigned)tid;
    __syncthreads();
    for (int k = 2; k <= 512; k <<= 1) {
        for (int j = k >> 1; j > 0; j >>= 1) {
            int ixj = tid ^ j;
            if (ixj > tid) {
                unsigned a = s_key[tid], b = s_key[ixj];
                bool up = ((tid & k) == 0);
                if (up ? (a > b) : (a < b)) { s_key[tid] = b; s_key[ixj] = a; }
            }
            __syncthreads();
        }
    }
    unsigned key = s_key[tid];
    int j = (int)(key & 0xFFFFu);
    g_sel_j[tid] = j;
    g_sel_desc[tid] = decode(s_selcol[j]);
}

// ---------------- gather ----------------------------------------------------
__global__ void __launch_bounds__(512, 2)
gather_kernel(const float* __restrict__ z_flat,
              const float* __restrict__ z_mean,
              const float* __restrict__ z_std,
              const float* __restrict__ x_poly_mean,
              const float* __restrict__ x_poly_std,
              const int* __restrict__ feature_mask,
              float* __restrict__ out) {
    __shared__ float s_zn[8][128];
    __shared__ float s_zp[8][32];
    __shared__ float s_d[8][120];
    __shared__ float s_out[8][512];
    const int tid = threadIdx.x;
    const int desc = g_sel_desc[tid];
    const int j = g_sel_j[tid];
    const int m = feature_mask[j];
    const float mj = x_poly_mean[m];
    const float sji = frcp(x_poly_std[m]);

    const int r0 = tid >> 7, c0 = tid & 127;
    const float zma = z_mean[c0];
    const float zsia = frcp(z_std[c0]);
    const int bp = tid % 120, br = tid / 120;
    int bi = 0, bj = 0;
    if (tid < 480) triu_pair(bp, 16, bi, bj);
    const bool zkeep = ((c0 & 7) < 2);
    const int zslot = ((c0 >> 3) << 1) | (c0 & 7);

    float za = z_flat[(blockIdx.x * 8 + r0) * 128 + c0];
    float zb = z_flat[(blockIdx.x * 8 + r0 + 4) * 128 + c0];
    for (int g = blockIdx.x; g < NG8; g += GRID_P) {
        float zac = fminf(fmaxf(za, -1e6f), 1e6f);
        float zbc = fminf(fmaxf(zb, -1e6f), 1e6f);
        s_zn[r0][c0]     = (zac - zma) * zsia;
        s_zn[r0 + 4][c0] = (zbc - zma) * zsia;
        if (zkeep) { s_zp[r0][zslot] = zac; s_zp[r0 + 4][zslot] = zbc; }
        __syncthreads();
        int gn = g + GRID_P;
        float za_n = 0.f, zb_n = 0.f;
        if (gn < NG8) {
            za_n = z_flat[(gn * 8 + r0) * 128 + c0];
            zb_n = z_flat[(gn * 8 + r0 + 4) * 128 + c0];
        }
        if (tid < 480) {
            s_d[br][bp]     = pbc_dist(s_zp[br], bi, bj);
            s_d[br + 4][bp] = pbc_dist(s_zp[br + 4], bi, bj);
        }
        __syncthreads();
        #pragma unroll
        for (int r = 0; r < 8; r++) {
            float v = evalcol(desc, s_zn[r], s_d[r]);
            if (isnan(v)) v = 0.0f;
            else if (isinf(v)) v = (v > 0.0f) ? 1e9f : -1e9f;
            v = fminf(fmaxf(v, -1e12f), 1e12f);
            s_out[r][j] = (v - mj) * sji;
        }
        __syncthreads();
        #pragma unroll
        for (int w = 0; w < 2; w++) {
            int f = tid + w * 512;            // float4 index within 8x512 tile
            int r = f >> 7, c4 = f & 127;
            float4 wv = *(const float4*)&s_out[r][c4 * 4];
            *(float4*)&out[(size_t)(g * 8 + r) * 512 + c4 * 4] = wv;
        }
        za = za_n; zb = zb_n;
    }
}

extern "C" void kernel_launch(void* const* d_in, const int* in_sizes, int n_in,
                              void* d_out, int out_size) {
    const float* z_flat      = (const float*)d_in[0];
    const float* z_mean      = (const float*)d_in[1];
    const float* z_std       = (const float*)d_in[2];
    const float* x_poly_mean = (const float*)d_in[3];
    const float* x_poly_std  = (const float*)d_in[4];
    const int*   feature_mask = (const int*)d_in[5];
    float* out = (float*)d_out;

    pass1_kernel<<<2 * GRID_P, 512>>>(z_flat, z_mean, z_std);
    reduce1_kernel<<<(8 * NVAL + 1023) / 1024, 1024>>>();
    keys_kernel<<<16, 256>>>();
    rank_kernel<<<128, 128>>>();
    scatter_kernel<<<16, 256>>>();
    sel_kernel<<<1, 512>>>(feature_mask);
    gather_kernel<<<GRID_P, 512>>>(z_flat, z_mean, z_std,
                                   x_poly_mean, x_poly_std, feature_mask, out);
}

// round 9
// speedup vs baseline: 4.8255x; 1.0872x over previous
#include <cuda_runtime.h>
#include <math.h>

#define NCOLS 3872
#define NROWS 32768
#define NG8   (NROWS / 8)
#define NG16  (NROWS / 16)
#define GRID_P 296
#define NDV 3360            // 120 pairs * 28 (14 sum + 14 sumsq)
#define NRV 2192            // non-dist columns
#define NVAL (NDV + 2 * NRV)   // 7744
#define CHUNK 37               // 296 / 8

__device__ float  g_scr_d[GRID_P * NDV];
__device__ float  g_scr_r[GRID_P * NRV * 2];
__device__ double g_part[8 * NVAL];
__device__ unsigned long long g_key[4096];
__device__ int    g_rank[4096];
__device__ int    g_top[1000];
__device__ int    g_sel_desc[512];
__device__ int    g_sel_j[512];

__device__ __forceinline__ float frcp(float x) {
    float r; asm("rcp.approx.f32 %0, %1;" : "=f"(r) : "f"(x)); return r;
}
__device__ __forceinline__ float fsqrt_a(float x) {
    float r; asm("sqrt.approx.f32 %0, %1;" : "=f"(r) : "f"(x)); return r;
}

__device__ __forceinline__ void triu_pair(int p, int n, int &i, int &j) {
    int ii = 0, rem = p, cnt = n - 1;
    while (rem >= cnt) { rem -= cnt; cnt--; ii++; }
    i = ii; j = ii + 1 + rem;
}

// Column descriptor: kind<<24 | a<<12 | b
__device__ __forceinline__ int decode(int c) {
    int kind, a, b = 0;
    if (c < 128)       { kind = 0; a = c; }
    else if (c < 1808) { int q = c - 128; kind = 16 + q / 120; a = q % 120; }
    else if (c < 1936) { kind = 1; a = c - 1808; }
    else if (c < 2064) { kind = 2; a = c - 1936; }
    else if (c < 2192) { kind = 3; a = c - 2064; }
    else if (c < 2320) { kind = 4; a = c - 2192; }
    else if (c < 2448) { kind = 5; a = c - 2320; }
    else if (c < 2464) { kind = 6; a = (c - 2448) * 8; }
    else if (c < 2912) {
        int idx = c - 2464; int n = idx / 28, pr = idx % 28;
        int i, j; triu_pair(pr, 8, i, j);
        kind = 7; a = n * 8 + i; b = n * 8 + j;
    } else {
        int idx = c - 2912; int pr = idx / 8, k = idx % 8;
        int i, j; triu_pair(pr, 16, i, j);
        kind = 7; a = i * 8 + k; b = j * 8 + k;
    }
    return (kind << 24) | (a << 12) | b;
}

__device__ __forceinline__ float evalrest(int desc, const float* __restrict__ zn) {
    int kind = desc >> 24;
    int a = (desc >> 12) & 0xFFF;
    int b = desc & 0xFFF;
    float v;
    switch (kind) {
        case 0: v = zn[a]; break;
        case 1: { float t = zn[a]; v = t * t; } break;
        case 2: v = __sinf(zn[a]); break;
        case 3: v = __cosf(zn[a]); break;
        case 4: v = __logf(fabsf(zn[a]) + 1e-3f); break;
        case 5: v = __expf(fminf(fmaxf(zn[a], -10.0f), 2.0f)); break;
        case 6: { float s = 0.0f;
                  #pragma unroll
                  for (int k = 4; k < 8; k++) { float t = zn[a + k]; s += t * t; }
                  v = s; } break;
        default: v = zn[a] * zn[b]; break;
    }
    return v;
}

__device__ __forceinline__ float evalcol(int desc, const float* __restrict__ zn,
                                         const float* __restrict__ dv) {
    int kind = desc >> 24;
    if (kind >= 16) {
        int a = (desc >> 12) & 0xFFF;
        float dd = dv[a];
        float v;
        switch (kind - 16) {
            case 0: v = dd; break;
            case 1: v = frcp(dd + 1e-3f); break;
            case 2: v = frcp(dd * dd + 1e-3f); break;
            case 3: { float d2 = dd * dd; v = frcp(d2 * dd + 1e-3f); } break;
            case 4: { float d2 = dd * dd; v = frcp(d2 * d2 + 1e-3f); } break;
            case 5: { float d2 = dd * dd; v = frcp(d2 * d2 * dd + 1e-3f); } break;
            case 6: { float d2 = dd * dd; float d4 = d2 * d2; v = frcp(d4 * d2 + 1e-3f); } break;
            case 7: { float d2 = dd * dd; float d4 = d2 * d2; v = frcp(d4 * d4 + 1e-3f); } break;
            case 8: { float d2 = dd * dd; float d4 = d2 * d2; v = frcp(d4 * d4 * d2 + 1e-3f); } break;
            case 9: { float d2 = dd * dd; float d4 = d2 * d2; v = frcp(d4 * d4 * d4 + 1e-3f); } break;
            case 10:{ float d2 = dd * dd; float d4 = d2 * d2; float d8 = d4 * d4;
                      v = frcp(d8 * d4 * d2 + 1e-3f); } break;
            case 11: v = __expf(-dd); break;
            case 12: v = __expf(-dd) * frcp(dd + 1e-3f); break;
            default: v = __logf(dd + 1e-3f); break;
        }
        return fminf(fmaxf(v, -1e6f), 1e6f);
    }
    return evalrest(desc, zn);
}

// distance power chain: accumulate 14 values + squares for distance d
__device__ __forceinline__ void dchain(float d, float acc[28]) {
    float dpe = d + 1e-3f;
    float r1 = frcp(dpe);
    float d2 = d * d, d3 = d2 * d, d4 = d2 * d2, d6 = d3 * d3, d8 = d4 * d4;
    float v[14];
    v[0] = d;
    v[1] = r1;
    v[2] = frcp(d2 + 1e-3f);
    v[3] = frcp(d3 + 1e-3f);
    v[4] = frcp(d4 + 1e-3f);
    v[5] = frcp(d4 * d + 1e-3f);
    v[6] = frcp(d6 + 1e-3f);
    v[7] = frcp(d8 + 1e-3f);
    v[8] = frcp(d8 * d2 + 1e-3f);
    v[9] = frcp(d6 * d6 + 1e-3f);
    v[10] = frcp(d8 * d6 + 1e-3f);
    float e = __expf(-d);
    v[11] = e;
    v[12] = e * r1;
    v[13] = __logf(dpe);
    #pragma unroll
    for (int k = 0; k < 14; k++) {
        acc[k] += v[k];
        acc[14 + k] = fmaf(v[k], v[k], acc[14 + k]);
    }
}

__device__ __forceinline__ float pbc_dist(const float* zp, int bi, int bj) {
    float dx = zp[2 * bi]     - zp[2 * bj];
    float dy = zp[2 * bi + 1] - zp[2 * bj + 1];
    dx -= 10.0f * rintf(dx * 0.1f);
    dy -= 10.0f * rintf(dy * 0.1f);
    return fsqrt_a(dx * dx + dy * dy) + 1e-6f;
}

// ---------------- pass 1a: distance-derived columns (16 rows/iter) ---------
__global__ void __launch_bounds__(512, 2)
p1dist_kernel(const float* __restrict__ z_flat) {
    __shared__ float s_zp[16][32];
    __shared__ float s_red[NDV];
    const int tid = threadIdx.x;
    const int bid = blockIdx.x;
    const int r0 = tid >> 7, c0 = tid & 127;
    const int bp = tid % 120, br = tid / 120;
    int bi = 0, bj = 0;
    if (tid < 480) triu_pair(bp, 16, bi, bj);
    const bool zkeep = ((c0 & 7) < 2);
    const int zslot = ((c0 >> 3) << 1) | (c0 & 7);

    float acc[28];
    #pragma unroll
    for (int k = 0; k < 28; k++) acc[k] = 0.f;

    float z[4];
    #pragma unroll
    for (int q = 0; q < 4; q++)
        z[q] = z_flat[(bid * 16 + r0 + 4 * q) * 128 + c0];
    for (int g = bid; g < NG16; g += GRID_P) {
        if (zkeep) {
            #pragma unroll
            for (int q = 0; q < 4; q++)
                s_zp[r0 + 4 * q][zslot] = fminf(fmaxf(z[q], -1e6f), 1e6f);
        }
        __syncthreads();
        int gn = g + GRID_P;
        float zn_[4];
        #pragma unroll
        for (int q = 0; q < 4; q++)
            zn_[q] = (gn < NG16) ? z_flat[(gn * 16 + r0 + 4 * q) * 128 + c0] : 0.f;
        if (tid < 480) {
            #pragma unroll
            for (int q = 0; q < 4; q++)
                dchain(pbc_dist(s_zp[br + 4 * q], bi, bj), acc);
        }
        __syncthreads();
        #pragma unroll
        for (int q = 0; q < 4; q++) z[q] = zn_[q];
    }
    if (tid < 480 && br == 0) {
        #pragma unroll
        for (int k = 0; k < 28; k++) s_red[bp * 28 + k] = acc[k];
    }
    __syncthreads();
    for (int s = 1; s < 4; s++) {
        if (tid < 480 && br == s) {
            #pragma unroll
            for (int k = 0; k < 28; k++) s_red[bp * 28 + k] += acc[k];
        }
        __syncthreads();
    }
    for (int v = tid; v < NDV; v += 512)
        g_scr_d[bid * NDV + v] = s_red[v];
}

// ---------------- pass 1b: non-distance columns (16 rows/iter) -------------
__global__ void __launch_bounds__(512, 2)
p1rest_kernel(const float* __restrict__ z_flat,
              const float* __restrict__ z_mean,
              const float* __restrict__ z_std) {
    __shared__ float s_zn[16][128];
    const int tid = threadIdx.x;
    const int bid = blockIdx.x;
    const int r0 = tid >> 7, c0 = tid & 127;
    const float zma = z_mean[c0];
    const float zsia = frcp(z_std[c0]);

    int desc[5]; bool val[5];
    #pragma unroll
    for (int k = 0; k < 5; k++) {
        int i = tid + k * 512;
        val[k] = (i < NRV);
        int col = (i < 128) ? i : i + 1680;
        desc[k] = val[k] ? decode(col) : 0;
    }
    float fs[5], fq[5];
    #pragma unroll
    for (int k = 0; k < 5; k++) { fs[k] = 0.f; fq[k] = 0.f; }

    float z[4];
    #pragma unroll
    for (int q = 0; q < 4; q++)
        z[q] = z_flat[(bid * 16 + r0 + 4 * q) * 128 + c0];
    for (int g = bid; g < NG16; g += GRID_P) {
        #pragma unroll
        for (int q = 0; q < 4; q++)
            s_zn[r0 + 4 * q][c0] = (fminf(fmaxf(z[q], -1e6f), 1e6f) - zma) * zsia;
        __syncthreads();
        int gn = g + GRID_P;
        float zn_[4];
        #pragma unroll
        for (int q = 0; q < 4; q++)
            zn_[q] = (gn < NG16) ? z_flat[(gn * 16 + r0 + 4 * q) * 128 + c0] : 0.f;
        #pragma unroll
        for (int r = 0; r < 16; r++) {
            const float* zn = s_zn[r];
            #pragma unroll
            for (int k = 0; k < 5; k++) {
                if (val[k]) {
                    float v = evalrest(desc[k], zn);
                    fs[k] += v;
                    fq[k] = fmaf(v, v, fq[k]);
                }
            }
        }
        __syncthreads();
        #pragma unroll
        for (int q = 0; q < 4; q++) z[q] = zn_[q];
    }
    #pragma unroll
    for (int k = 0; k < 5; k++) {
        int i = tid + k * 512;
        if (val[k]) {
            g_scr_r[bid * (2 * NRV) + i] = fs[k];
            g_scr_r[bid * (2 * NRV) + NRV + i] = fq[k];
        }
    }
}

// ---------------- reduce stage 1: 296 partials -> 8 f64 chunks -------------
__global__ void __launch_bounds__(1024, 2)
reduce1_kernel() {
    int t = blockIdx.x * 1024 + threadIdx.x;
    int chunk = t / NVAL;
    int v = t - chunk * NVAL;
    if (chunk >= 8) return;
    double s = 0.0;
    int b0 = chunk * CHUNK;
    if (v < NDV) {
        #pragma unroll 4
        for (int b = b0; b < b0 + CHUNK; b++) s += (double)g_scr_d[b * NDV + v];
    } else {
        int i = v - NDV;
        #pragma unroll 4
        for (int b = b0; b < b0 + CHUNK; b++) s += (double)g_scr_r[b * (2 * NRV) + i];
    }
    g_part[chunk * NVAL + v] = s;
}

// ---------------- keys: fold 8 partials -> monotone u64 key; zero ranks ----
__global__ void __launch_bounds__(256, 4)
keys_kernel() {
    int c = blockIdx.x * 256 + threadIdx.x;
    if (c >= 4096) return;
    g_rank[c] = 0;
    unsigned long long key = 0ull;
    if (c < NCOLS) {
        int vs, vq;
        if (c < 128)        { vs = NDV + c; vq = NDV + NRV + c; }
        else if (c < 1808)  { int q = c - 128; int kk = q / 120; int pr = q % 120;
                              vs = pr * 28 + kk; vq = vs + 14; }
        else                { int i = c - 1680; vs = NDV + i; vq = NDV + NRV + i; }
        double s = 0.0, qq = 0.0;
        #pragma unroll
        for (int ch = 0; ch < 8; ch++) {
            s  += g_part[ch * NVAL + vs];
            qq += g_part[ch * NVAL + vq];
        }
        double var = (qq - s * (s * (1.0 / 32768.0))) * (1.0 / 32767.0);
        float fv = (float)var;
        unsigned u = __float_as_uint(fv);
        u = (u & 0x80000000u) ? ~u : (u | 0x80000000u);
        key = ((unsigned long long)u << 32) |
              (unsigned long long)(0xFFFFFFFFu - (unsigned)c);
    }
    g_key[c] = key;
}

// ---------------- rank: 2-D tiled counting (16 cand-groups x 8 slices) -----
__global__ void __launch_bounds__(256, 4)
rank_kernel() {
    __shared__ unsigned long long sk[512];
    const int tid = threadIdx.x;
    const int cg = blockIdx.x & 15;       // candidate group (256 candidates)
    const int sl = blockIdx.x >> 4;       // key slice (512 keys)
    for (int i = tid; i < 512; i += 256) sk[i] = g_key[sl * 512 + i];
    __syncthreads();
    int c = cg * 256 + tid;
    unsigned long long mykey = g_key[c];
    int r = 0;
    #pragma unroll 8
    for (int i = 0; i < 512; i++) r += (sk[i] > mykey);
    if (r > 0) atomicAdd(&g_rank[c], r);
}

// ---------------- scatter: rank -> top table --------------------------------
__global__ void __launch_bounds__(256, 4)
scatter_kernel() {
    int c = blockIdx.x * 256 + threadIdx.x;
    if (c < NCOLS) {
        int r = g_rank[c];
        if (r < 1000) g_top[r] = c;
    }
}

// ---------------- selection + class sort ------------------------------------
__global__ void __launch_bounds__(512, 1)
sel_kernel(const int* __restrict__ feature_mask) {
    __shared__ int s_selcol[512];
    __shared__ unsigned s_key[512];
    const int tid = threadIdx.x;
    int colid = g_top[feature_mask[tid]];
    s_selcol[tid] = colid;
    unsigned cls = (unsigned)(decode(colid) >> 24);
    s_key[tid] = (cls << 16) | (unsigned)tid;
    __syncthreads();
    for (int k = 2; k <= 512; k <<= 1) {
        for (int j = k >> 1; j > 0; j >>= 1) {
            int ixj = tid ^ j;
            if (ixj > tid) {
                unsigned a = s_key[tid], b = s_key[ixj];
                bool up = ((tid & k) == 0);
                if (up ? (a > b) : (a < b)) { s_key[tid] = b; s_key[ixj] = a; }
            }
            __syncthreads();
        }
    }
    unsigned key = s_key[tid];
    int j = (int)(key & 0xFFFFu);
    g_sel_j[tid] = j;
    g_sel_desc[tid] = decode(s_selcol[j]);
}

// ---------------- gather (8 rows/iter) ---------------------------------------
__global__ void __launch_bounds__(512, 2)
gather_kernel(const float* __restrict__ z_flat,
              const float* __restrict__ z_mean,
              const float* __restrict__ z_std,
              const float* __restrict__ x_poly_mean,
              const float* __restrict__ x_poly_std,
              const int* __restrict__ feature_mask,
              float* __restrict__ out) {
    __shared__ float s_zn[8][128];
    __shared__ float s_zp[8][32];
    __shared__ float s_d[8][120];
    __shared__ float s_out[8][512];
    const int tid = threadIdx.x;
    const int desc = g_sel_desc[tid];
    const int j = g_sel_j[tid];
    const int m = feature_mask[j];
    const float mj = x_poly_mean[m];
    const float sji = frcp(x_poly_std[m]);

    const int r0 = tid >> 7, c0 = tid & 127;
    const float zma = z_mean[c0];
    const float zsia = frcp(z_std[c0]);
    const int bp = tid % 120, br = tid / 120;
    int bi = 0, bj = 0;
    if (tid < 480) triu_pair(bp, 16, bi, bj);
    const bool zkeep = ((c0 & 7) < 2);
    const int zslot = ((c0 >> 3) << 1) | (c0 & 7);

    float za = z_flat[(blockIdx.x * 8 + r0) * 128 + c0];
    float zb = z_flat[(blockIdx.x * 8 + r0 + 4) * 128 + c0];
    for (int g = blockIdx.x; g < NG8; g += GRID_P) {
        float zac = fminf(fmaxf(za, -1e6f), 1e6f);
        float zbc = fminf(fmaxf(zb, -1e6f), 1e6f);
        s_zn[r0][c0]     = (zac - zma) * zsia;
        s_zn[r0 + 4][c0] = (zbc - zma) * zsia;
        if (zkeep) { s_zp[r0][zslot] = zac; s_zp[r0 + 4][zslot] = zbc; }
        __syncthreads();
        int gn = g + GRID_P;
        float za_n = 0.f, zb_n = 0.f;
        if (gn < NG8) {
            za_n = z_flat[(gn * 8 + r0) * 128 + c0];
            zb_n = z_flat[(gn * 8 + r0 + 4) * 128 + c0];
        }
        if (tid < 480) {
            s_d[br][bp]     = pbc_dist(s_zp[br], bi, bj);
            s_d[br + 4][bp] = pbc_dist(s_zp[br + 4], bi, bj);
        }
        __syncthreads();
        #pragma unroll
        for (int r = 0; r < 8; r++) {
            float v = evalcol(desc, s_zn[r], s_d[r]);
            if (isnan(v)) v = 0.0f;
            else if (isinf(v)) v = (v > 0.0f) ? 1e9f : -1e9f;
            v = fminf(fmaxf(v, -1e12f), 1e12f);
            s_out[r][j] = (v - mj) * sji;
        }
        __syncthreads();
        #pragma unroll
        for (int w = 0; w < 2; w++) {
            int f = tid + w * 512;            // float4 index within 8x512 tile
            int r = f >> 7, c4 = f & 127;
            float4 wv = *(const float4*)&s_out[r][c4 * 4];
            *(float4*)&out[(size_t)(g * 8 + r) * 512 + c4 * 4] = wv;
        }
        za = za_n; zb = zb_n;
    }
}

extern "C" void kernel_launch(void* const* d_in, const int* in_sizes, int n_in,
                              void* d_out, int out_size) {
    const float* z_flat      = (const float*)d_in[0];
    const float* z_mean      = (const float*)d_in[1];
    const float* z_std       = (const float*)d_in[2];
    const float* x_poly_mean = (const float*)d_in[3];
    const float* x_poly_std  = (const float*)d_in[4];
    const int*   feature_mask = (const int*)d_in[5];
    float* out = (float*)d_out;

    p1dist_kernel<<<GRID_P, 512>>>(z_flat);
    p1rest_kernel<<<GRID_P, 512>>>(z_flat, z_mean, z_std);
    reduce1_kernel<<<(8 * NVAL + 1023) / 1024, 1024>>>();
    keys_kernel<<<16, 256>>>();
    rank_kernel<<<128, 256>>>();
    scatter_kernel<<<16, 256>>>();
    sel_kernel<<<1, 512>>>(feature_mask);
    gather_kernel<<<GRID_P, 512>>>(z_flat, z_mean, z_std,
                                   x_poly_mean, x_poly_std, feature_mask, out);
}